// round 9
// baseline (speedup 1.0000x reference)
#include <cuda_runtime.h>
#include <math.h>

// Problem constants (fixed shapes)
#define BB   16
#define IC   128
#define OC   128
#define HH   128
#define WW   128
#define EE   16
#define HWSZ (HH*WW)            // 16384
#define KK   9
#define OIK  (OC*IC*KK)         // 147456

// ---------------- device scratch (static, no runtime alloc) ----------------
__device__ float g_p  [BB*IC];                 // pooled x
__device__ float g_rw [BB*EE];                 // routing weights (softmax)
__device__ float g_w  [(size_t)BB*OIK];        // per-sample conv weights  (9.4 MB)
__device__ float g_out[(size_t)BB*OC*HWSZ];    // conv output              (134 MB)
__device__ float g_cp [BB*OC];                 // per-(b,o) sums for SE
__device__ float g_cw [BB*OC];                 // SE channel weights
__device__ float g_mean[BB*HWSZ];              // spatial-attn mean map
__device__ float g_max [BB*HWSZ];              // spatial-attn max map
__device__ float g_sw [BB*HWSZ];               // spatial-attn sigmoid map

__device__ __forceinline__ float bn_scale(float g) {
    return g * rsqrtf(1.0f + 1e-5f);
}
__device__ __forceinline__ float sigmoidf_(float v) {
    return 1.0f / (1.0f + __expf(-v));
}

// ---------------- K1: global average pool of x -> g_p ----------------
__global__ void k_pool(const float* __restrict__ x) {
    int b = blockIdx.x >> 7;
    int c = blockIdx.x & 127;
    const float* p = x + ((size_t)b * IC + c) * HWSZ;
    float s = 0.0f;
    for (int i = threadIdx.x; i < HWSZ; i += 256) s += p[i];
    __shared__ float sm[256];
    sm[threadIdx.x] = s;
    __syncthreads();
    for (int st = 128; st > 0; st >>= 1) {
        if (threadIdx.x < st) sm[threadIdx.x] += sm[threadIdx.x + st];
        __syncthreads();
    }
    if (threadIdx.x == 0) g_p[b * IC + c] = sm[0] * (1.0f / HWSZ);
}

// ---------------- K2: routing MLP + softmax (1 block) ----------------
__global__ void k_route(const float* __restrict__ rw1, const float* __restrict__ g1, const float* __restrict__ b1,
                        const float* __restrict__ rw2, const float* __restrict__ g2, const float* __restrict__ b2,
                        const float* __restrict__ rw3, const float* __restrict__ rb3) {
    __shared__ float sp[BB*IC];
    __shared__ float sh[BB*EE];
    __shared__ float sg[BB*IC];
    __shared__ float sl[BB*EE];
    int t = threadIdx.x;
    for (int i = t; i < BB*IC; i += 256) sp[i] = g_p[i];
    for (int i = t; i < BB*OC; i += 256) g_cp[i] = 0.0f;   // zero SE accumulators
    __syncthreads();
    {   // h = relu(bn(p @ rw1^T))   [16,16]
        int b = t >> 4, j = t & 15;
        float a = 0.0f;
        for (int i = 0; i < IC; i++) a += sp[b*IC + i] * rw1[j*IC + i];
        a = a * bn_scale(g1[j]) + b1[j];
        sh[t] = fmaxf(a, 0.0f);
    }
    __syncthreads();
    for (int k = 0; k < 8; k++) {  // g = sigmoid(bn(h @ rw2^T)) [16,128]
        int idx = t + k*256;
        int b = idx >> 7, i = idx & 127;
        float a = 0.0f;
        for (int j = 0; j < EE; j++) a += sh[b*EE + j] * rw2[i*EE + j];
        a = a * bn_scale(g2[i]) + b2[i];
        sg[idx] = sigmoidf_(a);
    }
    __syncthreads();
    {   // logits = g @ rw3^T + rb3  [16,16]
        int b = t >> 4, e = t & 15;
        float a = rb3[e];
        for (int i = 0; i < IC; i++) a += sg[b*IC + i] * rw3[e*IC + i];
        sl[t] = a;
    }
    __syncthreads();
    {   // softmax over e
        int b = t >> 4;
        float m = -1e30f;
        for (int k = 0; k < EE; k++) m = fmaxf(m, sl[b*EE + k]);
        float s = 0.0f;
        for (int k = 0; k < EE; k++) s += __expf(sl[b*EE + k] - m);
        g_rw[t] = __expf(sl[t] - m) / s;
    }
}

// ---------------- K3: expert-weighted kernel generation ----------------
__global__ void k_wgen(const float* __restrict__ experts) {
    __shared__ float srw[BB*EE];
    int t = threadIdx.x;
    srw[t] = g_rw[t];
    __syncthreads();
    int idx = blockIdx.x * 256 + t;        // 0 .. OIK-1
    float acc[BB];
#pragma unroll
    for (int b = 0; b < BB; b++) acc[b] = 0.0f;
    for (int e = 0; e < EE; e++) {
        float ev = experts[(size_t)e * OIK + idx];
#pragma unroll
        for (int b = 0; b < BB; b++) acc[b] += srw[b*EE + e] * ev;
    }
#pragma unroll
    for (int b = 0; b < BB; b++) g_w[(size_t)b * OIK + idx] = acc[b];
}

// ---------------- K4: per-sample 3x3 conv (main compute) ----------------
// block: 32x32 spatial tile, 16 output channels, one b.
// 256 threads as 16x16; each thread -> 2x2 px * 16 o (64 accumulators).
__global__ void __launch_bounds__(256) k_conv(const float* __restrict__ x) {
    __shared__ float xs[34*34];
    __shared__ float ws[16*9];
    __shared__ float s_cp[16];
    int bz = blockIdx.z;
    int b = bz >> 3;
    int obase = (bz & 7) << 4;
    int h0 = blockIdx.y * 32, w0 = blockIdx.x * 32;
    int tid = threadIdx.x;
    int ty = tid >> 4, tx = tid & 15;

    float acc[16][4];
#pragma unroll
    for (int o = 0; o < 16; o++)
#pragma unroll
        for (int p = 0; p < 4; p++) acc[o][p] = 0.0f;
    if (tid < 16) s_cp[tid] = 0.0f;

    const float* xb = x + (size_t)b * IC * HWSZ;
    const float* wb = g_w + ((size_t)b * OC + obase) * IC * KK;

    for (int ic = 0; ic < IC; ic++) {
        const float* xc = xb + (size_t)ic * HWSZ;
        for (int i = tid; i < 34*34; i += 256) {
            int r = i / 34, c = i - r * 34;
            int hh = h0 - 1 + r, ww = w0 - 1 + c;
            xs[i] = (hh >= 0 && hh < HH && ww >= 0 && ww < WW) ? xc[hh*WW + ww] : 0.0f;
        }
        if (tid < 144) {
            int o = tid / 9, k = tid - o * 9;
            ws[tid] = wb[((size_t)o * IC + ic) * KK + k];
        }
        __syncthreads();

        float xr[4][4];
#pragma unroll
        for (int r = 0; r < 4; r++)
#pragma unroll
            for (int c = 0; c < 4; c++)
                xr[r][c] = xs[(2*ty + r) * 34 + 2*tx + c];

#pragma unroll
        for (int o = 0; o < 16; o++) {
            float w00 = ws[o*9+0], w01 = ws[o*9+1], w02 = ws[o*9+2];
            float w10 = ws[o*9+3], w11 = ws[o*9+4], w12 = ws[o*9+5];
            float w20 = ws[o*9+6], w21 = ws[o*9+7], w22 = ws[o*9+8];
#pragma unroll
            for (int py = 0; py < 2; py++)
#pragma unroll
                for (int px = 0; px < 2; px++) {
                    float v = acc[o][py*2+px];
                    v += xr[py+0][px+0]*w00 + xr[py+0][px+1]*w01 + xr[py+0][px+2]*w02;
                    v += xr[py+1][px+0]*w10 + xr[py+1][px+1]*w11 + xr[py+1][px+2]*w12;
                    v += xr[py+2][px+0]*w20 + xr[py+2][px+1]*w21 + xr[py+2][px+2]*w22;
                    acc[o][py*2+px] = v;
                }
        }
        __syncthreads();
    }

    // write out + per-(b,o) channel sums for SE
    float* ob = g_out + ((size_t)b * OC + obase) * HWSZ;
#pragma unroll
    for (int o = 0; o < 16; o++) {
        float s = acc[o][0] + acc[o][1] + acc[o][2] + acc[o][3];
        // warp-level reduce first to cut smem atomics 32x
        for (int off = 16; off > 0; off >>= 1)
            s += __shfl_down_sync(0xffffffffu, s, off);
        if ((tid & 31) == 0) atomicAdd(&s_cp[o], s);
#pragma unroll
        for (int py = 0; py < 2; py++)
#pragma unroll
            for (int px = 0; px < 2; px++) {
                int h = h0 + 2*ty + py, w = w0 + 2*tx + px;
                ob[(size_t)o * HWSZ + h*WW + w] = acc[o][py*2+px];
            }
    }
    __syncthreads();
    if (tid < 16) atomicAdd(&g_cp[b*OC + obase + tid], s_cp[tid]);
}

// ---------------- K5: SE channel attention MLP (1 block) ----------------
__global__ void k_chattn(const float* __restrict__ w1, const float* __restrict__ g1, const float* __restrict__ b1,
                         const float* __restrict__ w2, const float* __restrict__ g2, const float* __restrict__ b2) {
    __shared__ float scp[BB*OC];
    __shared__ float sh[BB*16];
    int t = threadIdx.x;
    for (int i = t; i < BB*OC; i += 256) scp[i] = g_cp[i] * (1.0f / HWSZ);
    __syncthreads();
    {
        int b = t >> 4, j = t & 15;
        float a = 0.0f;
        for (int i = 0; i < OC; i++) a += scp[b*OC + i] * w1[j*OC + i];
        a = a * bn_scale(g1[j]) + b1[j];
        sh[t] = fmaxf(a, 0.0f);
    }
    __syncthreads();
    for (int k = 0; k < 8; k++) {
        int idx = t + k*256;
        int b = idx >> 7, i = idx & 127;
        float a = 0.0f;
        for (int j = 0; j < 16; j++) a += sh[b*16 + j] * w2[i*16 + j];
        a = a * bn_scale(g2[i]) + b2[i];
        g_cw[idx] = sigmoidf_(a);
    }
}

// ---------------- K6: spatial mean/max over channels of out*cw ----------------
__global__ void k_spstats() {
    __shared__ float scw[OC];
    int blk = blockIdx.x;
    int b = blk >> 6;                        // 64 blocks per batch
    int t = threadIdx.x;
    if (t < OC) scw[t] = g_cw[b*OC + t];
    __syncthreads();
    int hw = (blk & 63) * 256 + t;
    const float* ob = g_out + (size_t)b * OC * HWSZ + hw;
    float s = 0.0f, m = -1e30f;
    for (int o = 0; o < OC; o++) {
        float v = ob[(size_t)o * HWSZ] * scw[o];
        s += v;
        m = fmaxf(m, v);
    }
    g_mean[b*HWSZ + hw] = s * (1.0f / OC);
    g_max [b*HWSZ + hw] = m;
}

// ---------------- K7: 7x7 spatial-attention conv + sigmoid(bn) ----------------
__global__ void k_spconv(const float* __restrict__ saw, const float* __restrict__ sg, const float* __restrict__ sb) {
    __shared__ float sw_[98];
    int t = threadIdx.x;
    if (t < 98) sw_[t] = saw[t];
    __syncthreads();
    int idx = blockIdx.x * 256 + t;
    int b = idx >> 14;
    int hw = idx & 16383;
    int h = hw >> 7, w = hw & 127;
    float a = 0.0f;
    const float* mb = g_mean + (size_t)b * HWSZ;
    const float* xb = g_max  + (size_t)b * HWSZ;
    for (int kh = 0; kh < 7; kh++) {
        int hh = h + kh - 3;
        if (hh < 0 || hh >= HH) continue;
        for (int kw = 0; kw < 7; kw++) {
            int ww = w + kw - 3;
            if (ww < 0 || ww >= WW) continue;
            int o = hh*WW + ww;
            a += mb[o] * sw_[kh*7 + kw] + xb[o] * sw_[49 + kh*7 + kw];
        }
    }
    a = a * bn_scale(sg[0]) + sb[0];
    g_sw[idx] = sigmoidf_(a);
}

// ---------------- K8: final out = conv*cw*sw + x ----------------
__global__ void k_final(const float* __restrict__ x, float* __restrict__ out) {
    size_t i4 = (size_t)blockIdx.x * 256 + threadIdx.x;   // over float4 lanes
    size_t e = i4 * 4;
    int b  = (int)(e >> 21);
    int o  = (int)((e >> 14) & 127);
    int hw = (int)(e & 16383);
    float cw = g_cw[b*OC + o];
    float4 v  = *(const float4*)(g_out + e);
    float4 xv = ((const float4*)x)[i4];
    float4 sv = *(const float4*)(g_sw + (size_t)b*HWSZ + hw);
    float4 r;
    r.x = v.x * cw * sv.x + xv.x;
    r.y = v.y * cw * sv.y + xv.y;
    r.z = v.z * cw * sv.z + xv.z;
    r.w = v.w * cw * sv.w + xv.w;
    ((float4*)out)[i4] = r;
}

// ---------------- launcher ----------------
extern "C" void kernel_launch(void* const* d_in, const int* in_sizes, int n_in,
                              void* d_out, int out_size) {
    const float* x        = (const float*)d_in[0];
    const float* experts  = (const float*)d_in[1];
    const float* rw1      = (const float*)d_in[2];
    const float* rbn1_g   = (const float*)d_in[3];
    const float* rbn1_b   = (const float*)d_in[4];
    const float* rw2      = (const float*)d_in[5];
    const float* rbn2_g   = (const float*)d_in[6];
    const float* rbn2_b   = (const float*)d_in[7];
    const float* rw3      = (const float*)d_in[8];
    const float* rb3      = (const float*)d_in[9];
    const float* ca_w1    = (const float*)d_in[10];
    const float* ca_bn1_g = (const float*)d_in[11];
    const float* ca_bn1_b = (const float*)d_in[12];
    const float* ca_w2    = (const float*)d_in[13];
    const float* ca_bn2_g = (const float*)d_in[14];
    const float* ca_bn2_b = (const float*)d_in[15];
    const float* sa_w     = (const float*)d_in[16];
    const float* sa_bn_g  = (const float*)d_in[17];
    const float* sa_bn_b  = (const float*)d_in[18];
    float* out = (float*)d_out;

    k_pool<<<BB*IC, 256>>>(x);
    k_route<<<1, 256>>>(rw1, rbn1_g, rbn1_b, rw2, rbn2_g, rbn2_b, rw3, rb3);
    k_wgen<<<OIK/256, 256>>>(experts);
    {
        dim3 grid(WW/32, HH/32, BB*8);
        k_conv<<<grid, 256>>>(x);
    }
    k_chattn<<<1, 256>>>(ca_w1, ca_bn1_g, ca_bn1_b, ca_w2, ca_bn2_g, ca_bn2_b);
    k_spstats<<<BB*64, 256>>>();
    k_spconv<<<BB*64, 256>>>(sa_w, sa_bn_g, sa_bn_b);
    k_final<<<(BB*OC*HWSZ)/(4*256), 256>>>(x, out);
}

// round 10
// speedup vs baseline: 1.0012x; 1.0012x over previous
#include <cuda_runtime.h>
#include <math.h>

// Problem constants (fixed shapes)
#define BB   16
#define IC   128
#define OC   128
#define HH   128
#define WW   128
#define EE   16
#define HWSZ (HH*WW)            // 16384
#define KK   9
#define OIK  (OC*IC*KK)         // 147456

// ---------------- device scratch (static, no runtime alloc) ----------------
__device__ float g_p  [BB*IC];                 // pooled x
__device__ float g_rw [BB*EE];                 // routing weights (softmax)
__device__ float g_w  [(size_t)BB*OIK];        // per-sample conv weights  (9.4 MB)
__device__ float g_out[(size_t)BB*OC*HWSZ];    // conv output              (134 MB)
__device__ float g_cp [BB*OC];                 // per-(b,o) sums for SE
__device__ float g_cw [BB*OC];                 // SE channel weights
__device__ float g_mean[BB*HWSZ];              // spatial-attn mean map
__device__ float g_max [BB*HWSZ];              // spatial-attn max map
__device__ float g_sw [BB*HWSZ];               // spatial-attn sigmoid map

__device__ __forceinline__ float bn_scale(float g) {
    return g * rsqrtf(1.0f + 1e-5f);
}
__device__ __forceinline__ float sigmoidf_(float v) {
    return 1.0f / (1.0f + __expf(-v));
}

// ---------------- K1: global average pool of x -> g_p ----------------
__global__ void k_pool(const float* __restrict__ x) {
    int b = blockIdx.x >> 7;
    int c = blockIdx.x & 127;
    const float* p = x + ((size_t)b * IC + c) * HWSZ;
    float s = 0.0f;
    for (int i = threadIdx.x; i < HWSZ; i += 256) s += p[i];
    __shared__ float sm[256];
    sm[threadIdx.x] = s;
    __syncthreads();
    for (int st = 128; st > 0; st >>= 1) {
        if (threadIdx.x < st) sm[threadIdx.x] += sm[threadIdx.x + st];
        __syncthreads();
    }
    if (threadIdx.x == 0) g_p[b * IC + c] = sm[0] * (1.0f / HWSZ);
}

// ---------------- K2: routing MLP + softmax (1 block) ----------------
__global__ void k_route(const float* __restrict__ rw1, const float* __restrict__ g1, const float* __restrict__ b1,
                        const float* __restrict__ rw2, const float* __restrict__ g2, const float* __restrict__ b2,
                        const float* __restrict__ rw3, const float* __restrict__ rb3) {
    __shared__ float sp[BB*IC];
    __shared__ float sh[BB*EE];
    __shared__ float sg[BB*IC];
    __shared__ float sl[BB*EE];
    int t = threadIdx.x;
    for (int i = t; i < BB*IC; i += 256) sp[i] = g_p[i];
    for (int i = t; i < BB*OC; i += 256) g_cp[i] = 0.0f;   // zero SE accumulators
    __syncthreads();
    {   // h = relu(bn(p @ rw1^T))   [16,16]
        int b = t >> 4, j = t & 15;
        float a = 0.0f;
        for (int i = 0; i < IC; i++) a += sp[b*IC + i] * rw1[j*IC + i];
        a = a * bn_scale(g1[j]) + b1[j];
        sh[t] = fmaxf(a, 0.0f);
    }
    __syncthreads();
    for (int k = 0; k < 8; k++) {  // g = sigmoid(bn(h @ rw2^T)) [16,128]
        int idx = t + k*256;
        int b = idx >> 7, i = idx & 127;
        float a = 0.0f;
        for (int j = 0; j < EE; j++) a += sh[b*EE + j] * rw2[i*EE + j];
        a = a * bn_scale(g2[i]) + b2[i];
        sg[idx] = sigmoidf_(a);
    }
    __syncthreads();
    {   // logits = g @ rw3^T + rb3  [16,16]
        int b = t >> 4, e = t & 15;
        float a = rb3[e];
        for (int i = 0; i < IC; i++) a += sg[b*IC + i] * rw3[e*IC + i];
        sl[t] = a;
    }
    __syncthreads();
    {   // softmax over e
        int b = t >> 4;
        float m = -1e30f;
        for (int k = 0; k < EE; k++) m = fmaxf(m, sl[b*EE + k]);
        float s = 0.0f;
        for (int k = 0; k < EE; k++) s += __expf(sl[b*EE + k] - m);
        g_rw[t] = __expf(sl[t] - m) / s;
    }
}

// ---------------- K3: expert-weighted kernel generation ----------------
__global__ void k_wgen(const float* __restrict__ experts) {
    __shared__ float srw[BB*EE];
    int t = threadIdx.x;
    srw[t] = g_rw[t];
    __syncthreads();
    int idx = blockIdx.x * 256 + t;        // 0 .. OIK-1
    float acc[BB];
#pragma unroll
    for (int b = 0; b < BB; b++) acc[b] = 0.0f;
    for (int e = 0; e < EE; e++) {
        float ev = experts[(size_t)e * OIK + idx];
#pragma unroll
        for (int b = 0; b < BB; b++) acc[b] += srw[b*EE + e] * ev;
    }
#pragma unroll
    for (int b = 0; b < BB; b++) g_w[(size_t)b * OIK + idx] = acc[b];
}

// ---------------- K4: per-sample 3x3 conv (main compute) ----------------
// block: 32x32 spatial tile, 16 output channels, one b.
// 256 threads as 16x16; each thread -> 2x2 px * 16 o (64 accumulators).
__global__ void __launch_bounds__(256) k_conv(const float* __restrict__ x) {
    __shared__ float xs[34*34];
    __shared__ float ws[16*9];
    __shared__ float s_cp[16];
    int bz = blockIdx.z;
    int b = bz >> 3;
    int obase = (bz & 7) << 4;
    int h0 = blockIdx.y * 32, w0 = blockIdx.x * 32;
    int tid = threadIdx.x;
    int ty = tid >> 4, tx = tid & 15;

    float acc[16][4];
#pragma unroll
    for (int o = 0; o < 16; o++)
#pragma unroll
        for (int p = 0; p < 4; p++) acc[o][p] = 0.0f;
    if (tid < 16) s_cp[tid] = 0.0f;

    const float* xb = x + (size_t)b * IC * HWSZ;
    const float* wb = g_w + ((size_t)b * OC + obase) * IC * KK;

    for (int ic = 0; ic < IC; ic++) {
        const float* xc = xb + (size_t)ic * HWSZ;
        for (int i = tid; i < 34*34; i += 256) {
            int r = i / 34, c = i - r * 34;
            int hh = h0 - 1 + r, ww = w0 - 1 + c;
            xs[i] = (hh >= 0 && hh < HH && ww >= 0 && ww < WW) ? xc[hh*WW + ww] : 0.0f;
        }
        if (tid < 144) {
            int o = tid / 9, k = tid - o * 9;
            ws[tid] = wb[((size_t)o * IC + ic) * KK + k];
        }
        __syncthreads();

        float xr[4][4];
#pragma unroll
        for (int r = 0; r < 4; r++)
#pragma unroll
            for (int c = 0; c < 4; c++)
                xr[r][c] = xs[(2*ty + r) * 34 + 2*tx + c];

#pragma unroll
        for (int o = 0; o < 16; o++) {
            float w00 = ws[o*9+0], w01 = ws[o*9+1], w02 = ws[o*9+2];
            float w10 = ws[o*9+3], w11 = ws[o*9+4], w12 = ws[o*9+5];
            float w20 = ws[o*9+6], w21 = ws[o*9+7], w22 = ws[o*9+8];
#pragma unroll
            for (int py = 0; py < 2; py++)
#pragma unroll
                for (int px = 0; px < 2; px++) {
                    float v = acc[o][py*2+px];
                    v += xr[py+0][px+0]*w00 + xr[py+0][px+1]*w01 + xr[py+0][px+2]*w02;
                    v += xr[py+1][px+0]*w10 + xr[py+1][px+1]*w11 + xr[py+1][px+2]*w12;
                    v += xr[py+2][px+0]*w20 + xr[py+2][px+1]*w21 + xr[py+2][px+2]*w22;
                    acc[o][py*2+px] = v;
                }
        }
        __syncthreads();
    }

    // write out + per-(b,o) channel sums for SE
    float* ob = g_out + ((size_t)b * OC + obase) * HWSZ;
#pragma unroll
    for (int o = 0; o < 16; o++) {
        float s = acc[o][0] + acc[o][1] + acc[o][2] + acc[o][3];
        // warp-level reduce first to cut smem atomics 32x
        for (int off = 16; off > 0; off >>= 1)
            s += __shfl_down_sync(0xffffffffu, s, off);
        if ((tid & 31) == 0) atomicAdd(&s_cp[o], s);
#pragma unroll
        for (int py = 0; py < 2; py++)
#pragma unroll
            for (int px = 0; px < 2; px++) {
                int h = h0 + 2*ty + py, w = w0 + 2*tx + px;
                ob[(size_t)o * HWSZ + h*WW + w] = acc[o][py*2+px];
            }
    }
    __syncthreads();
    if (tid < 16) atomicAdd(&g_cp[b*OC + obase + tid], s_cp[tid]);
}

// ---------------- K5: SE channel attention MLP (1 block) ----------------
__global__ void k_chattn(const float* __restrict__ w1, const float* __restrict__ g1, const float* __restrict__ b1,
                         const float* __restrict__ w2, const float* __restrict__ g2, const float* __restrict__ b2) {
    __shared__ float scp[BB*OC];
    __shared__ float sh[BB*16];
    int t = threadIdx.x;
    for (int i = t; i < BB*OC; i += 256) scp[i] = g_cp[i] * (1.0f / HWSZ);
    __syncthreads();
    {
        int b = t >> 4, j = t & 15;
        float a = 0.0f;
        for (int i = 0; i < OC; i++) a += scp[b*OC + i] * w1[j*OC + i];
        a = a * bn_scale(g1[j]) + b1[j];
        sh[t] = fmaxf(a, 0.0f);
    }
    __syncthreads();
    for (int k = 0; k < 8; k++) {
        int idx = t + k*256;
        int b = idx >> 7, i = idx & 127;
        float a = 0.0f;
        for (int j = 0; j < 16; j++) a += sh[b*16 + j] * w2[i*16 + j];
        a = a * bn_scale(g2[i]) + b2[i];
        g_cw[idx] = sigmoidf_(a);
    }
}

// ---------------- K6: spatial mean/max over channels of out*cw ----------------
__global__ void k_spstats() {
    __shared__ float scw[OC];
    int blk = blockIdx.x;
    int b = blk >> 6;                        // 64 blocks per batch
    int t = threadIdx.x;
    if (t < OC) scw[t] = g_cw[b*OC + t];
    __syncthreads();
    int hw = (blk & 63) * 256 + t;
    const float* ob = g_out + (size_t)b * OC * HWSZ + hw;
    float s = 0.0f, m = -1e30f;
    for (int o = 0; o < OC; o++) {
        float v = ob[(size_t)o * HWSZ] * scw[o];
        s += v;
        m = fmaxf(m, v);
    }
    g_mean[b*HWSZ + hw] = s * (1.0f / OC);
    g_max [b*HWSZ + hw] = m;
}

// ---------------- K7: 7x7 spatial-attention conv + sigmoid(bn) ----------------
__global__ void k_spconv(const float* __restrict__ saw, const float* __restrict__ sg, const float* __restrict__ sb) {
    __shared__ float sw_[98];
    int t = threadIdx.x;
    if (t < 98) sw_[t] = saw[t];
    __syncthreads();
    int idx = blockIdx.x * 256 + t;
    int b = idx >> 14;
    int hw = idx & 16383;
    int h = hw >> 7, w = hw & 127;
    float a = 0.0f;
    const float* mb = g_mean + (size_t)b * HWSZ;
    const float* xb = g_max  + (size_t)b * HWSZ;
    for (int kh = 0; kh < 7; kh++) {
        int hh = h + kh - 3;
        if (hh < 0 || hh >= HH) continue;
        for (int kw = 0; kw < 7; kw++) {
            int ww = w + kw - 3;
            if (ww < 0 || ww >= WW) continue;
            int o = hh*WW + ww;
            a += mb[o] * sw_[kh*7 + kw] + xb[o] * sw_[49 + kh*7 + kw];
        }
    }
    a = a * bn_scale(sg[0]) + sb[0];
    g_sw[idx] = sigmoidf_(a);
}

// ---------------- K8: final out = conv*cw*sw + x ----------------
__global__ void k_final(const float* __restrict__ x, float* __restrict__ out) {
    size_t i4 = (size_t)blockIdx.x * 256 + threadIdx.x;   // over float4 lanes
    size_t e = i4 * 4;
    int b  = (int)(e >> 21);
    int o  = (int)((e >> 14) & 127);
    int hw = (int)(e & 16383);
    float cw = g_cw[b*OC + o];
    float4 v  = *(const float4*)(g_out + e);
    float4 xv = ((const float4*)x)[i4];
    float4 sv = *(const float4*)(g_sw + (size_t)b*HWSZ + hw);
    float4 r;
    r.x = v.x * cw * sv.x + xv.x;
    r.y = v.y * cw * sv.y + xv.y;
    r.z = v.z * cw * sv.z + xv.z;
    r.w = v.w * cw * sv.w + xv.w;
    ((float4*)out)[i4] = r;
}

// ---------------- launcher ----------------
extern "C" void kernel_launch(void* const* d_in, const int* in_sizes, int n_in,
                              void* d_out, int out_size) {
    const float* x        = (const float*)d_in[0];
    const float* experts  = (const float*)d_in[1];
    const float* rw1      = (const float*)d_in[2];
    const float* rbn1_g   = (const float*)d_in[3];
    const float* rbn1_b   = (const float*)d_in[4];
    const float* rw2      = (const float*)d_in[5];
    const float* rbn2_g   = (const float*)d_in[6];
    const float* rbn2_b   = (const float*)d_in[7];
    const float* rw3      = (const float*)d_in[8];
    const float* rb3      = (const float*)d_in[9];
    const float* ca_w1    = (const float*)d_in[10];
    const float* ca_bn1_g = (const float*)d_in[11];
    const float* ca_bn1_b = (const float*)d_in[12];
    const float* ca_w2    = (const float*)d_in[13];
    const float* ca_bn2_g = (const float*)d_in[14];
    const float* ca_bn2_b = (const float*)d_in[15];
    const float* sa_w     = (const float*)d_in[16];
    const float* sa_bn_g  = (const float*)d_in[17];
    const float* sa_bn_b  = (const float*)d_in[18];
    float* out = (float*)d_out;

    k_pool<<<BB*IC, 256>>>(x);
    k_route<<<1, 256>>>(rw1, rbn1_g, rbn1_b, rw2, rbn2_g, rbn2_b, rw3, rb3);
    k_wgen<<<OIK/256, 256>>>(experts);
    {
        dim3 grid(WW/32, HH/32, BB*8);
        k_conv<<<grid, 256>>>(x);
    }
    k_chattn<<<1, 256>>>(ca_w1, ca_bn1_g, ca_bn1_b, ca_w2, ca_bn2_g, ca_bn2_b);
    k_spstats<<<BB*64, 256>>>();
    k_spconv<<<BB*64, 256>>>(sa_w, sa_bn_g, sa_bn_b);
    k_final<<<(BB*OC*HWSZ)/(4*256), 256>>>(x, out);
}

// round 12
// speedup vs baseline: 3.0980x; 3.0942x over previous
#include <cuda_runtime.h>
#include <math.h>
#include <stdint.h>

// Problem constants (fixed shapes)
#define BB   16
#define IC   128
#define OC   128
#define HH   128
#define WW   128
#define EE   16
#define HWSZ (HH*WW)            // 16384
#define KK   9
#define OIK  (OC*IC*KK)         // 147456

// ---------------- device scratch (static, no runtime alloc) ----------------
__device__ float g_p  [BB*IC];                 // pooled x
__device__ float g_rw [BB*EE];                 // routing weights (softmax)
__device__ float g_w  [(size_t)BB*OIK];        // per-sample weights, layout [b][tap][o][ic], tf32-rounded
__device__ float g_out[(size_t)BB*OC*HWSZ];    // conv output              (134 MB)
__device__ float g_cp [BB*OC];                 // per-(b,o) sums for SE
__device__ float g_cw [BB*OC];                 // SE channel weights
__device__ float g_mean[BB*HWSZ];              // spatial-attn mean map
__device__ float g_max [BB*HWSZ];              // spatial-attn max map
__device__ float g_sw [BB*HWSZ];               // spatial-attn sigmoid map

__device__ __forceinline__ float bn_scale(float g) {
    return g * rsqrtf(1.0f + 1e-5f);
}
__device__ __forceinline__ float sigmoidf_(float v) {
    return 1.0f / (1.0f + __expf(-v));
}

// ---------------- K1: global average pool of x -> g_p ----------------
__global__ void k_pool(const float* __restrict__ x) {
    int b = blockIdx.x >> 7;
    int c = blockIdx.x & 127;
    const float* p = x + ((size_t)b * IC + c) * HWSZ;
    float s = 0.0f;
    for (int i = threadIdx.x; i < HWSZ; i += 256) s += p[i];
    __shared__ float sm[256];
    sm[threadIdx.x] = s;
    __syncthreads();
    for (int st = 128; st > 0; st >>= 1) {
        if (threadIdx.x < st) sm[threadIdx.x] += sm[threadIdx.x + st];
        __syncthreads();
    }
    if (threadIdx.x == 0) g_p[b * IC + c] = sm[0] * (1.0f / HWSZ);
}

// ---------------- K2: routing MLP + softmax (1 block) ----------------
__global__ void k_route(const float* __restrict__ rw1, const float* __restrict__ g1, const float* __restrict__ b1,
                        const float* __restrict__ rw2, const float* __restrict__ g2, const float* __restrict__ b2,
                        const float* __restrict__ rw3, const float* __restrict__ rb3) {
    __shared__ float sp[BB*IC];
    __shared__ float sh[BB*EE];
    __shared__ float sg[BB*IC];
    __shared__ float sl[BB*EE];
    int t = threadIdx.x;
    for (int i = t; i < BB*IC; i += 256) sp[i] = g_p[i];
    for (int i = t; i < BB*OC; i += 256) g_cp[i] = 0.0f;   // zero SE accumulators
    __syncthreads();
    {
        int b = t >> 4, j = t & 15;
        float a = 0.0f;
        for (int i = 0; i < IC; i++) a += sp[b*IC + i] * rw1[j*IC + i];
        a = a * bn_scale(g1[j]) + b1[j];
        sh[t] = fmaxf(a, 0.0f);
    }
    __syncthreads();
    for (int k = 0; k < 8; k++) {
        int idx = t + k*256;
        int b = idx >> 7, i = idx & 127;
        float a = 0.0f;
        for (int j = 0; j < EE; j++) a += sh[b*EE + j] * rw2[i*EE + j];
        a = a * bn_scale(g2[i]) + b2[i];
        sg[idx] = sigmoidf_(a);
    }
    __syncthreads();
    {
        int b = t >> 4, e = t & 15;
        float a = rb3[e];
        for (int i = 0; i < IC; i++) a += sg[b*IC + i] * rw3[e*IC + i];
        sl[t] = a;
    }
    __syncthreads();
    {
        int b = t >> 4;
        float m = -1e30f;
        for (int k = 0; k < EE; k++) m = fmaxf(m, sl[b*EE + k]);
        float s = 0.0f;
        for (int k = 0; k < EE; k++) s += __expf(sl[b*EE + k] - m);
        g_rw[t] = __expf(sl[t] - m) / s;
    }
}

// ---------------- K3: expert-weighted kernel generation ----------------
// Writes g_w in layout [b][tap][o][ic], values pre-rounded to tf32 (rna).
__global__ void k_wgen(const float* __restrict__ experts) {
    __shared__ float srw[BB*EE];
    int t = threadIdx.x;
    srw[t] = g_rw[t];
    __syncthreads();
    int idx = blockIdx.x * 256 + t;          // 0 .. 16383 over (o,ic)
    int o  = idx >> 7;
    int ic = idx & 127;
    const float* eb = experts + ((size_t)o * IC + ic) * KK;
    for (int k = 0; k < KK; k++) {
        float acc[BB];
#pragma unroll
        for (int b2 = 0; b2 < BB; b2++) acc[b2] = 0.0f;
        for (int e = 0; e < EE; e++) {
            float ev = eb[(size_t)e * OIK + k];
#pragma unroll
            for (int b2 = 0; b2 < BB; b2++) acc[b2] += srw[b2*EE + e] * ev;
        }
#pragma unroll
        for (int b2 = 0; b2 < BB; b2++) {
            uint32_t u;
            asm("cvt.rna.tf32.f32 %0, %1;" : "=r"(u) : "f"(acc[b2]));
            g_w[(((size_t)b2 * KK + k) * OC + o) * IC + ic] = __uint_as_float(u);
        }
    }
}

// ---------------- K4: per-sample 3x3 conv via mma.sync tf32 implicit GEMM ----------------
// CTA = (b, row h). M=128 (o) x N=128 (px) x K=1152. 8 warps 4(M)x2(N), warp tile 32x64.
#define XS_ICS 392                    // 3*130 + 2 pad -> B-frag banks (8t+g) conflict-free
#define AS_STR 36                     // A row stride  -> A-frag banks (4g+t) conflict-free
#define XS_WORDS (32*XS_ICS)          // 12544
#define AS_WORDS (128*AS_STR)         // 4608 per buffer
#define CONV_SMEM ((XS_WORDS + 2*AS_WORDS)*4)   // 87040 bytes

#define CPA16(dst, src) asm volatile("cp.async.ca.shared.global [%0], [%1], 16;" :: "r"(dst), "l"(src) : "memory")
#define CPC()           asm volatile("cp.async.commit_group;" ::: "memory")
#define CPW0()          asm volatile("cp.async.wait_group 0;" ::: "memory")

#define MMA_TF32(dd, A0, A1, A2, A3, B0, B1) \
    asm volatile("mma.sync.aligned.m16n8k8.row.col.f32.tf32.tf32.f32 " \
                 "{%0,%1,%2,%3}, {%4,%5,%6,%7}, {%8,%9}, {%0,%1,%2,%3};" \
                 : "+f"((dd)[0]), "+f"((dd)[1]), "+f"((dd)[2]), "+f"((dd)[3]) \
                 : "r"(__float_as_uint(A0)), "r"(__float_as_uint(A1)), \
                   "r"(__float_as_uint(A2)), "r"(__float_as_uint(A3)), \
                   "r"(__float_as_uint(B0)), "r"(__float_as_uint(B1)))

__global__ void __launch_bounds__(256, 2) k_conv_mma(const float* __restrict__ x) {
    extern __shared__ float smem[];
    float* xs = smem;                  // [32 ic][392]
    float* As = smem + XS_WORDS;       // [2][128 o][36]
    uint32_t as_u32 = (uint32_t)__cvta_generic_to_shared(As);

    int tid  = threadIdx.x;
    int lane = tid & 31, wid = tid >> 5;
    int g = lane >> 2, t = lane & 3;
    int om0 = (wid & 3) * 32;
    int pn0 = (wid >> 2) * 64;
    int b = blockIdx.x >> 7;
    int h = blockIdx.x & 127;

    const float* xb  = x   + (size_t)b * IC * HWSZ;
    const float* wkb = g_w + (size_t)b * KK * OC * IC;

    float d[2][8][4];
#pragma unroll
    for (int mf = 0; mf < 2; mf++)
#pragma unroll
        for (int nf = 0; nf < 8; nf++)
#pragma unroll
            for (int r = 0; r < 4; r++) d[mf][nf][r] = 0.0f;

    for (int chunk = 0; chunk < 4; chunk++) {
        __syncthreads();               // prior reads of xs/As done
        // ---- stage x rows h-1..h+1 for 32 ics (tf32 pre-rounded) ----
        const float* xc = xb + (size_t)chunk * 32 * HWSZ;
        for (int idx = tid; idx < 32*390; idx += 256) {
            int icc = idx / 390;
            int rem = idx - icc * 390;
            int r = rem / 130, c = rem - r * 130;
            int hin = h - 1 + r, win = c - 1;
            float v = 0.0f;
            if ((unsigned)hin < 128u && (unsigned)win < 128u)
                v = xc[(size_t)icc * HWSZ + hin * WW + win];
            uint32_t u;
            asm("cvt.rna.tf32.f32 %0, %1;" : "=r"(u) : "f"(v));
            xs[icc * XS_ICS + r * 130 + c] = __uint_as_float(u);
        }
        // ---- preload A (tap 0) into buffer 0 via cp.async ----
        {
            const float* asrc = wkb + chunk * 32;
#pragma unroll
            for (int it = 0; it < 4; it++) {
                int e4 = it * 256 + tid;
                int o = e4 >> 3, i4 = (e4 & 7) * 4;
                CPA16(as_u32 + (o * AS_STR + i4) * 4, asrc + o * IC + i4);
            }
            CPC();
        }
        CPW0();
        __syncthreads();

        for (int tap = 0; tap < 9; tap++) {
            int buf = tap & 1;
            if (tap < 8) {             // prefetch next tap's A into other buffer
                const float* asrc = wkb + (size_t)(tap + 1) * OC * IC + chunk * 32;
                uint32_t dbase = as_u32 + ((buf ^ 1) * AS_WORDS) * 4;
#pragma unroll
                for (int it = 0; it < 4; it++) {
                    int e4 = it * 256 + tid;
                    int o = e4 >> 3, i4 = (e4 & 7) * 4;
                    CPA16(dbase + (o * AS_STR + i4) * 4, asrc + o * IC + i4);
                }
                CPC();
            }
            int ky = tap / 3, kx = tap - ky * 3;
            const float* a_s = As + buf * AS_WORDS;
            const float* b_s = xs + ky * 130 + pn0 + g + kx;
#pragma unroll
            for (int kk = 0; kk < 4; kk++) {
                int kb = kk * 8;
                float a0[2], a1[2], a2[2], a3[2];
#pragma unroll
                for (int mf = 0; mf < 2; mf++) {
                    int ro = om0 + mf * 16 + g;
                    a0[mf] = a_s[ro * AS_STR + kb + t];
                    a1[mf] = a_s[(ro + 8) * AS_STR + kb + t];
                    a2[mf] = a_s[ro * AS_STR + kb + t + 4];
                    a3[mf] = a_s[(ro + 8) * AS_STR + kb + t + 4];
                }
                const float* bp = b_s + (kb + t) * XS_ICS;
#pragma unroll
                for (int nf = 0; nf < 8; nf++) {
                    float b0 = bp[nf * 8];
                    float b1 = bp[4 * XS_ICS + nf * 8];
                    MMA_TF32(d[0][nf], a0[0], a1[0], a2[0], a3[0], b0, b1);
                    MMA_TF32(d[1][nf], a0[1], a1[1], a2[1], a3[1], b0, b1);
                }
            }
            if (tap < 8) CPW0();
            __syncthreads();
        }
    }

    // ---- epilogue: store + fused SE channel sums ----
    float* ob = g_out + (size_t)b * OC * HWSZ + h * WW;
#pragma unroll
    for (int mf = 0; mf < 2; mf++) {
        int o0 = om0 + mf * 16 + g;
        float s0 = 0.0f, s1 = 0.0f;
#pragma unroll
        for (int nf = 0; nf < 8; nf++) {
            int px = pn0 + nf * 8 + t * 2;
            float2 v0 = make_float2(d[mf][nf][0], d[mf][nf][1]);
            float2 v1 = make_float2(d[mf][nf][2], d[mf][nf][3]);
            *(float2*)(ob + (size_t)o0 * HWSZ + px)       = v0;
            *(float2*)(ob + (size_t)(o0 + 8) * HWSZ + px) = v1;
            s0 += v0.x + v0.y;
            s1 += v1.x + v1.y;
        }
        s0 += __shfl_xor_sync(0xffffffffu, s0, 1);
        s0 += __shfl_xor_sync(0xffffffffu, s0, 2);
        s1 += __shfl_xor_sync(0xffffffffu, s1, 1);
        s1 += __shfl_xor_sync(0xffffffffu, s1, 2);
        if (t == 0) {
            atomicAdd(&g_cp[b * OC + o0], s0);
            atomicAdd(&g_cp[b * OC + o0 + 8], s1);
        }
    }
}

// ---------------- K5: SE channel attention MLP (1 block) ----------------
__global__ void k_chattn(const float* __restrict__ w1, const float* __restrict__ g1, const float* __restrict__ b1,
                         const float* __restrict__ w2, const float* __restrict__ g2, const float* __restrict__ b2) {
    __shared__ float scp[BB*OC];
    __shared__ float sh[BB*16];
    int t = threadIdx.x;
    for (int i = t; i < BB*OC; i += 256) scp[i] = g_cp[i] * (1.0f / HWSZ);
    __syncthreads();
    {
        int b = t >> 4, j = t & 15;
        float a = 0.0f;
        for (int i = 0; i < OC; i++) a += scp[b*OC + i] * w1[j*OC + i];
        a = a * bn_scale(g1[j]) + b1[j];
        sh[t] = fmaxf(a, 0.0f);
    }
    __syncthreads();
    for (int k = 0; k < 8; k++) {
        int idx = t + k*256;
        int b = idx >> 7, i = idx & 127;
        float a = 0.0f;
        for (int j = 0; j < 16; j++) a += sh[b*16 + j] * w2[i*16 + j];
        a = a * bn_scale(g2[i]) + b2[i];
        g_cw[idx] = sigmoidf_(a);
    }
}

// ---------------- K6: spatial mean/max over channels of out*cw ----------------
__global__ void k_spstats() {
    __shared__ float scw[OC];
    int blk = blockIdx.x;
    int b = blk >> 6;
    int t = threadIdx.x;
    if (t < OC) scw[t] = g_cw[b*OC + t];
    __syncthreads();
    int hw = (blk & 63) * 256 + t;
    const float* ob = g_out + (size_t)b * OC * HWSZ + hw;
    float s = 0.0f, m = -1e30f;
    for (int o = 0; o < OC; o++) {
        float v = ob[(size_t)o * HWSZ] * scw[o];
        s += v;
        m = fmaxf(m, v);
    }
    g_mean[b*HWSZ + hw] = s * (1.0f / OC);
    g_max [b*HWSZ + hw] = m;
}

// ---------------- K7: 7x7 spatial-attention conv + sigmoid(bn) ----------------
__global__ void k_spconv(const float* __restrict__ saw, const float* __restrict__ sg, const float* __restrict__ sb) {
    __shared__ float sw_[98];
    int t = threadIdx.x;
    if (t < 98) sw_[t] = saw[t];
    __syncthreads();
    int idx = blockIdx.x * 256 + t;
    int b = idx >> 14;
    int hw = idx & 16383;
    int h = hw >> 7, w = hw & 127;
    float a = 0.0f;
    const float* mb = g_mean + (size_t)b * HWSZ;
    const float* xb = g_max  + (size_t)b * HWSZ;
    for (int kh = 0; kh < 7; kh++) {
        int hh = h + kh - 3;
        if (hh < 0 || hh >= HH) continue;
        for (int kw = 0; kw < 7; kw++) {
            int ww = w + kw - 3;
            if (ww < 0 || ww >= WW) continue;
            int o = hh*WW + ww;
            a += mb[o] * sw_[kh*7 + kw] + xb[o] * sw_[49 + kh*7 + kw];
        }
    }
    a = a * bn_scale(sg[0]) + sb[0];
    g_sw[idx] = sigmoidf_(a);
}

// ---------------- K8: final out = conv*cw*sw + x ----------------
__global__ void k_final(const float* __restrict__ x, float* __restrict__ out) {
    size_t i4 = (size_t)blockIdx.x * 256 + threadIdx.x;
    size_t e = i4 * 4;
    int b  = (int)(e >> 21);
    int o  = (int)((e >> 14) & 127);
    int hw = (int)(e & 16383);
    float cw = g_cw[b*OC + o];
    float4 v  = *(const float4*)(g_out + e);
    float4 xv = ((const float4*)x)[i4];
    float4 sv = *(const float4*)(g_sw + (size_t)b*HWSZ + hw);
    float4 r;
    r.x = v.x * cw * sv.x + xv.x;
    r.y = v.y * cw * sv.y + xv.y;
    r.z = v.z * cw * sv.z + xv.z;
    r.w = v.w * cw * sv.w + xv.w;
    ((float4*)out)[i4] = r;
}

// ---------------- launcher ----------------
extern "C" void kernel_launch(void* const* d_in, const int* in_sizes, int n_in,
                              void* d_out, int out_size) {
    const float* x        = (const float*)d_in[0];
    const float* experts  = (const float*)d_in[1];
    const float* rw1      = (const float*)d_in[2];
    const float* rbn1_g   = (const float*)d_in[3];
    const float* rbn1_b   = (const float*)d_in[4];
    const float* rw2      = (const float*)d_in[5];
    const float* rbn2_g   = (const float*)d_in[6];
    const float* rbn2_b   = (const float*)d_in[7];
    const float* rw3      = (const float*)d_in[8];
    const float* rb3      = (const float*)d_in[9];
    const float* ca_w1    = (const float*)d_in[10];
    const float* ca_bn1_g = (const float*)d_in[11];
    const float* ca_bn1_b = (const float*)d_in[12];
    const float* ca_w2    = (const float*)d_in[13];
    const float* ca_bn2_g = (const float*)d_in[14];
    const float* ca_bn2_b = (const float*)d_in[15];
    const float* sa_w     = (const float*)d_in[16];
    const float* sa_bn_g  = (const float*)d_in[17];
    const float* sa_bn_b  = (const float*)d_in[18];
    float* out = (float*)d_out;

    cudaFuncSetAttribute(k_conv_mma, cudaFuncAttributeMaxDynamicSharedMemorySize, CONV_SMEM);

    k_pool<<<BB*IC, 256>>>(x);
    k_route<<<1, 256>>>(rw1, rbn1_g, rbn1_b, rw2, rbn2_g, rbn2_b, rw3, rb3);
    k_wgen<<<(OC*IC)/256, 256>>>(experts);
    k_conv_mma<<<BB*HH, 256, CONV_SMEM>>>(x);
    k_chattn<<<1, 256>>>(ca_w1, ca_bn1_g, ca_bn1_b, ca_w2, ca_bn2_g, ca_bn2_b);
    k_spstats<<<BB*64, 256>>>();
    k_spconv<<<BB*64, 256>>>(sa_w, sa_bn_g, sa_bn_b);
    k_final<<<(BB*OC*HWSZ)/(4*256), 256>>>(x, out);
}

// round 13
// speedup vs baseline: 5.1247x; 1.6542x over previous
#include <cuda_runtime.h>
#include <math.h>
#include <stdint.h>

// Problem constants (fixed shapes)
#define BB   16
#define IC   128
#define OC   128
#define HH   128
#define WW   128
#define EE   16
#define HWSZ (HH*WW)            // 16384
#define KK   9
#define OIK  (OC*IC*KK)         // 147456

// ---------------- device scratch (static, no runtime alloc) ----------------
__device__ float g_p  [BB*IC];                 // pooled x
__device__ float g_rw [BB*EE];                 // routing weights (softmax)
__device__ float g_w  [(size_t)BB*OIK];        // per-sample weights in MMA-fragment layout, tf32-rounded
__device__ float g_out[(size_t)BB*OC*HWSZ];    // conv output              (134 MB)
__device__ float g_cp [BB*OC];                 // per-(b,o) sums for SE
__device__ float g_cw [BB*OC];                 // SE channel weights
__device__ float g_mean[BB*HWSZ];              // spatial-attn mean map
__device__ float g_max [BB*HWSZ];              // spatial-attn max map
__device__ float g_sw [BB*HWSZ];               // spatial-attn sigmoid map

__device__ __forceinline__ float bn_scale(float g) {
    return g * rsqrtf(1.0f + 1e-5f);
}
__device__ __forceinline__ float sigmoidf_(float v) {
    return 1.0f / (1.0f + __expf(-v));
}

// ---------------- K1: global average pool of x -> g_p ----------------
__global__ void k_pool(const float* __restrict__ x) {
    int b = blockIdx.x >> 7;
    int c = blockIdx.x & 127;
    const float* p = x + ((size_t)b * IC + c) * HWSZ;
    float s = 0.0f;
    for (int i = threadIdx.x; i < HWSZ; i += 256) s += p[i];
    __shared__ float sm[256];
    sm[threadIdx.x] = s;
    __syncthreads();
    for (int st = 128; st > 0; st >>= 1) {
        if (threadIdx.x < st) sm[threadIdx.x] += sm[threadIdx.x + st];
        __syncthreads();
    }
    if (threadIdx.x == 0) g_p[b * IC + c] = sm[0] * (1.0f / HWSZ);
}

// ---------------- K2: routing MLP + softmax (1 block) ----------------
__global__ void k_route(const float* __restrict__ rw1, const float* __restrict__ g1, const float* __restrict__ b1,
                        const float* __restrict__ rw2, const float* __restrict__ g2, const float* __restrict__ b2,
                        const float* __restrict__ rw3, const float* __restrict__ rb3) {
    __shared__ float sp[BB*IC];
    __shared__ float sh[BB*EE];
    __shared__ float sg[BB*IC];
    __shared__ float sl[BB*EE];
    int t = threadIdx.x;
    for (int i = t; i < BB*IC; i += 256) sp[i] = g_p[i];
    for (int i = t; i < BB*OC; i += 256) g_cp[i] = 0.0f;   // zero SE accumulators
    __syncthreads();
    {
        int b = t >> 4, j = t & 15;
        float a = 0.0f;
        for (int i = 0; i < IC; i++) a += sp[b*IC + i] * rw1[j*IC + i];
        a = a * bn_scale(g1[j]) + b1[j];
        sh[t] = fmaxf(a, 0.0f);
    }
    __syncthreads();
    for (int k = 0; k < 8; k++) {
        int idx = t + k*256;
        int b = idx >> 7, i = idx & 127;
        float a = 0.0f;
        for (int j = 0; j < EE; j++) a += sh[b*EE + j] * rw2[i*EE + j];
        a = a * bn_scale(g2[i]) + b2[i];
        sg[idx] = sigmoidf_(a);
    }
    __syncthreads();
    {
        int b = t >> 4, e = t & 15;
        float a = rb3[e];
        for (int i = 0; i < IC; i++) a += sg[b*IC + i] * rw3[e*IC + i];
        sl[t] = a;
    }
    __syncthreads();
    {
        int b = t >> 4;
        float m = -1e30f;
        for (int k = 0; k < EE; k++) m = fmaxf(m, sl[b*EE + k]);
        float s = 0.0f;
        for (int k = 0; k < EE; k++) s += __expf(sl[b*EE + k] - m);
        g_rw[t] = __expf(sl[t] - m) / s;
    }
}

// ---------------- K3: expert-weighted kernel generation (fragment layout) ----------------
// g_w layout (float units): ((((chunk*9+tap)*4+kk)*4+m)*32+lane)*8 + mf*4 + j, per b plane of OIK.
// Fragment value j: o = m*32 + mf*16 + g + (j&1)*8 ; ic = chunk*32 + kk*8 + t + (j>>1)*4
// with g = lane>>2, t = lane&3. Values tf32-rounded (rna).
__global__ void k_wgen(const float* __restrict__ experts) {
    __shared__ float srw[BB*EE];
    int tid = threadIdx.x;
    srw[tid] = g_rw[tid];
    __syncthreads();
    int flat = blockIdx.x * 256 + tid;       // 0 .. 147455
    int chunk = flat / 36864;
    int r = flat - chunk * 36864;
    int tap = r / 4096;
    int r2 = r - tap * 4096;
    int kk = r2 >> 10;
    int m = (r2 >> 8) & 3;
    int lane = (r2 >> 3) & 31;
    int mf = (r2 >> 2) & 1;
    int j = r2 & 3;
    int g = lane >> 2, t = lane & 3;
    int o  = m*32 + mf*16 + g + (j & 1)*8;
    int ic = chunk*32 + kk*8 + t + (j >> 1)*4;

    const float* es = experts + ((size_t)o * IC + ic) * KK + tap;
    float acc[BB];
#pragma unroll
    for (int b2 = 0; b2 < BB; b2++) acc[b2] = 0.0f;
    for (int e = 0; e < EE; e++) {
        float ev = es[(size_t)e * OIK];
#pragma unroll
        for (int b2 = 0; b2 < BB; b2++) acc[b2] += srw[b2*EE + e] * ev;
    }
#pragma unroll
    for (int b2 = 0; b2 < BB; b2++) {
        uint32_t u;
        asm("cvt.rna.tf32.f32 %0, %1;" : "=r"(u) : "f"(acc[b2]));
        g_w[(size_t)b2 * OIK + flat] = __uint_as_float(u);
    }
}

// ---------------- K4: per-sample 3x3 conv via mma.sync tf32 implicit GEMM ----------------
// CTA = (b, row h). M=128 (o) x N=128 (px) x K=1152. 8 warps 4(M)x2(N), warp tile 32x64.
// A fragments loaded directly from global (fragment layout); B staged in smem once per ic-chunk.
#define XS_ICS 392                    // 3*130 + 2 pad -> B-frag banks (8t+g) conflict-free
#define XS_WORDS (32*XS_ICS)          // 12544
#define CONV_SMEM (XS_WORDS*4)        // 50176 bytes

#define MMA_TF32(dd, A0, A1, A2, A3, B0, B1) \
    asm volatile("mma.sync.aligned.m16n8k8.row.col.f32.tf32.tf32.f32 " \
                 "{%0,%1,%2,%3}, {%4,%5,%6,%7}, {%8,%9}, {%0,%1,%2,%3};" \
                 : "+f"((dd)[0]), "+f"((dd)[1]), "+f"((dd)[2]), "+f"((dd)[3]) \
                 : "r"(__float_as_uint(A0)), "r"(__float_as_uint(A1)), \
                   "r"(__float_as_uint(A2)), "r"(__float_as_uint(A3)), \
                   "r"(__float_as_uint(B0)), "r"(__float_as_uint(B1)))

__global__ void __launch_bounds__(256, 2) k_conv_mma(const float* __restrict__ x) {
    extern __shared__ float xs[];      // [32 ic][392]

    int tid  = threadIdx.x;
    int lane = tid & 31, wid = tid >> 5;
    int g = lane >> 2, t = lane & 3;
    int m4 = wid & 3;
    int om0 = m4 * 32;
    int pn0 = (wid >> 2) * 64;
    int b = blockIdx.x >> 7;
    int h = blockIdx.x & 127;

    const float*  xb   = x + (size_t)b * IC * HWSZ;
    const float4* g_w4 = (const float4*)(g_w + (size_t)b * OIK);

    float d[2][8][4];
#pragma unroll
    for (int mf = 0; mf < 2; mf++)
#pragma unroll
        for (int nf = 0; nf < 8; nf++)
#pragma unroll
            for (int r = 0; r < 4; r++) d[mf][nf][r] = 0.0f;

    const float* bwp = xs + t * XS_ICS + pn0 + g;   // B-frag base (per-thread)

    for (int chunk = 0; chunk < 4; chunk++) {
        __syncthreads();               // all warps done reading xs
        // ---- stage x rows h-1..h+1 for this 32-ic chunk (tf32 pre-rounded) ----
        const float* xc = xb + (size_t)chunk * 32 * HWSZ;
        for (int idx = tid; idx < 32*390; idx += 256) {
            int icc = idx / 390;
            int rem = idx - icc * 390;
            int r = rem / 130, c = rem - r * 130;
            int hin = h - 1 + r, win = c - 1;
            float v = 0.0f;
            if ((unsigned)hin < 128u && (unsigned)win < 128u)
                v = xc[(size_t)icc * HWSZ + hin * WW + win];
            uint32_t u;
            asm("cvt.rna.tf32.f32 %0, %1;" : "=r"(u) : "f"(v));
            xs[icc * XS_ICS + r * 130 + c] = __uint_as_float(u);
        }
        __syncthreads();

        // A fragment pointer for this (b, chunk): float4 units
        const float4* ap = g_w4 + (size_t)chunk * (9*1024) + m4 * 64 + lane * 2;

#pragma unroll
        for (int tap = 0; tap < 9; tap++) {
            const int ky = tap / 3, kx = tap - ky * 3;
            // load all A fragments for this tap (8 x LDG.128, coalesced, L2-hot)
            float4 Af[4][2];
            const float4* at = ap + tap * 1024;
#pragma unroll
            for (int kk = 0; kk < 4; kk++) {
                Af[kk][0] = at[kk*256];
                Af[kk][1] = at[kk*256 + 1];
            }
            const float* bt = bwp + ky * 130 + kx;
#pragma unroll
            for (int kk = 0; kk < 4; kk++) {
                const float* bp = bt + kk * 8 * XS_ICS;
#pragma unroll
                for (int nf = 0; nf < 8; nf++) {
                    float b0 = bp[nf * 8];
                    float b1 = bp[4 * XS_ICS + nf * 8];
                    MMA_TF32(d[0][nf], Af[kk][0].x, Af[kk][0].y, Af[kk][0].z, Af[kk][0].w, b0, b1);
                    MMA_TF32(d[1][nf], Af[kk][1].x, Af[kk][1].y, Af[kk][1].z, Af[kk][1].w, b0, b1);
                }
            }
        }
    }

    // ---- epilogue: store + fused SE channel sums ----
    float* ob = g_out + (size_t)b * OC * HWSZ + h * WW;
#pragma unroll
    for (int mf = 0; mf < 2; mf++) {
        int o0 = om0 + mf * 16 + g;
        float s0 = 0.0f, s1 = 0.0f;
#pragma unroll
        for (int nf = 0; nf < 8; nf++) {
            int px = pn0 + nf * 8 + t * 2;
            float2 v0 = make_float2(d[mf][nf][0], d[mf][nf][1]);
            float2 v1 = make_float2(d[mf][nf][2], d[mf][nf][3]);
            *(float2*)(ob + (size_t)o0 * HWSZ + px)       = v0;
            *(float2*)(ob + (size_t)(o0 + 8) * HWSZ + px) = v1;
            s0 += v0.x + v0.y;
            s1 += v1.x + v1.y;
        }
        s0 += __shfl_xor_sync(0xffffffffu, s0, 1);
        s0 += __shfl_xor_sync(0xffffffffu, s0, 2);
        s1 += __shfl_xor_sync(0xffffffffu, s1, 1);
        s1 += __shfl_xor_sync(0xffffffffu, s1, 2);
        if (t == 0) {
            atomicAdd(&g_cp[b * OC + o0], s0);
            atomicAdd(&g_cp[b * OC + o0 + 8], s1);
        }
    }
}

// ---------------- K5: SE channel attention MLP (1 block) ----------------
__global__ void k_chattn(const float* __restrict__ w1, const float* __restrict__ g1, const float* __restrict__ b1,
                         const float* __restrict__ w2, const float* __restrict__ g2, const float* __restrict__ b2) {
    __shared__ float scp[BB*OC];
    __shared__ float sh[BB*16];
    int t = threadIdx.x;
    for (int i = t; i < BB*OC; i += 256) scp[i] = g_cp[i] * (1.0f / HWSZ);
    __syncthreads();
    {
        int b = t >> 4, j = t & 15;
        float a = 0.0f;
        for (int i = 0; i < OC; i++) a += scp[b*OC + i] * w1[j*OC + i];
        a = a * bn_scale(g1[j]) + b1[j];
        sh[t] = fmaxf(a, 0.0f);
    }
    __syncthreads();
    for (int k = 0; k < 8; k++) {
        int idx = t + k*256;
        int b = idx >> 7, i = idx & 127;
        float a = 0.0f;
        for (int j = 0; j < 16; j++) a += sh[b*16 + j] * w2[i*16 + j];
        a = a * bn_scale(g2[i]) + b2[i];
        g_cw[idx] = sigmoidf_(a);
    }
}

// ---------------- K6: spatial mean/max over channels of out*cw ----------------
__global__ void k_spstats() {
    __shared__ float scw[OC];
    int blk = blockIdx.x;
    int b = blk >> 6;
    int t = threadIdx.x;
    if (t < OC) scw[t] = g_cw[b*OC + t];
    __syncthreads();
    int hw = (blk & 63) * 256 + t;
    const float* ob = g_out + (size_t)b * OC * HWSZ + hw;
    float s = 0.0f, m = -1e30f;
    for (int o = 0; o < OC; o++) {
        float v = ob[(size_t)o * HWSZ] * scw[o];
        s += v;
        m = fmaxf(m, v);
    }
    g_mean[b*HWSZ + hw] = s * (1.0f / OC);
    g_max [b*HWSZ + hw] = m;
}

// ---------------- K7: 7x7 spatial-attention conv + sigmoid(bn) ----------------
__global__ void k_spconv(const float* __restrict__ saw, const float* __restrict__ sg, const float* __restrict__ sb) {
    __shared__ float sw_[98];
    int t = threadIdx.x;
    if (t < 98) sw_[t] = saw[t];
    __syncthreads();
    int idx = blockIdx.x * 256 + t;
    int b = idx >> 14;
    int hw = idx & 16383;
    int h = hw >> 7, w = hw & 127;
    float a = 0.0f;
    const float* mb = g_mean + (size_t)b * HWSZ;
    const float* xb = g_max  + (size_t)b * HWSZ;
    for (int kh = 0; kh < 7; kh++) {
        int hh = h + kh - 3;
        if (hh < 0 || hh >= HH) continue;
        for (int kw = 0; kw < 7; kw++) {
            int ww = w + kw - 3;
            if (ww < 0 || ww >= WW) continue;
            int o = hh*WW + ww;
            a += mb[o] * sw_[kh*7 + kw] + xb[o] * sw_[49 + kh*7 + kw];
        }
    }
    a = a * bn_scale(sg[0]) + sb[0];
    g_sw[idx] = sigmoidf_(a);
}

// ---------------- K8: final out = conv*cw*sw + x ----------------
__global__ void k_final(const float* __restrict__ x, float* __restrict__ out) {
    size_t i4 = (size_t)blockIdx.x * 256 + threadIdx.x;
    size_t e = i4 * 4;
    int b  = (int)(e >> 21);
    int o  = (int)((e >> 14) & 127);
    int hw = (int)(e & 16383);
    float cw = g_cw[b*OC + o];
    float4 v  = *(const float4*)(g_out + e);
    float4 xv = ((const float4*)x)[i4];
    float4 sv = *(const float4*)(g_sw + (size_t)b*HWSZ + hw);
    float4 r;
    r.x = v.x * cw * sv.x + xv.x;
    r.y = v.y * cw * sv.y + xv.y;
    r.z = v.z * cw * sv.z + xv.z;
    r.w = v.w * cw * sv.w + xv.w;
    ((float4*)out)[i4] = r;
}

// ---------------- launcher ----------------
extern "C" void kernel_launch(void* const* d_in, const int* in_sizes, int n_in,
                              void* d_out, int out_size) {
    const float* x        = (const float*)d_in[0];
    const float* experts  = (const float*)d_in[1];
    const float* rw1      = (const float*)d_in[2];
    const float* rbn1_g   = (const float*)d_in[3];
    const float* rbn1_b   = (const float*)d_in[4];
    const float* rw2      = (const float*)d_in[5];
    const float* rbn2_g   = (const float*)d_in[6];
    const float* rbn2_b   = (const float*)d_in[7];
    const float* rw3      = (const float*)d_in[8];
    const float* rb3      = (const float*)d_in[9];
    const float* ca_w1    = (const float*)d_in[10];
    const float* ca_bn1_g = (const float*)d_in[11];
    const float* ca_bn1_b = (const float*)d_in[12];
    const float* ca_w2    = (const float*)d_in[13];
    const float* ca_bn2_g = (const float*)d_in[14];
    const float* ca_bn2_b = (const float*)d_in[15];
    const float* sa_w     = (const float*)d_in[16];
    const float* sa_bn_g  = (const float*)d_in[17];
    const float* sa_bn_b  = (const float*)d_in[18];
    float* out = (float*)d_out;

    cudaFuncSetAttribute(k_conv_mma, cudaFuncAttributeMaxDynamicSharedMemorySize, CONV_SMEM);

    k_pool<<<BB*IC, 256>>>(x);
    k_route<<<1, 256>>>(rw1, rbn1_g, rbn1_b, rw2, rbn2_g, rbn2_b, rw3, rb3);
    k_wgen<<<OIK/256, 256>>>(experts);
    k_conv_mma<<<BB*HH, 256, CONV_SMEM>>>(x);
    k_chattn<<<1, 256>>>(ca_w1, ca_bn1_g, ca_bn1_b, ca_w2, ca_bn2_g, ca_bn2_b);
    k_spstats<<<BB*64, 256>>>();
    k_spconv<<<BB*64, 256>>>(sa_w, sa_bn_g, sa_bn_b);
    k_final<<<(BB*OC*HWSZ)/(4*256), 256>>>(x, out);
}

// round 14
// speedup vs baseline: 6.4104x; 1.2509x over previous
#include <cuda_runtime.h>
#include <cuda_fp16.h>
#include <math.h>
#include <stdint.h>

// Problem constants (fixed shapes)
#define BB   16
#define IC   128
#define OC   128
#define HH   128
#define WW   128
#define EE   16
#define HWSZ (HH*WW)            // 16384
#define KK   9
#define OIK  (OC*IC*KK)         // 147456

// ---------------- device scratch (static, no runtime alloc) ----------------
__device__ float  g_p  [BB*IC];                 // pooled x
__device__ float  g_rw [BB*EE];                 // routing weights (softmax)
__device__ __half g_wh [(size_t)BB*OIK];        // per-sample weights, fp16 MMA-fragment layout (4.7 MB)
__device__ float  g_out[(size_t)BB*OC*HWSZ];    // conv output              (134 MB)
__device__ float  g_cp [BB*OC];                 // per-(b,o) sums for SE
__device__ float  g_cw [BB*OC];                 // SE channel weights
__device__ float  g_mean[BB*HWSZ];              // spatial-attn mean map
__device__ float  g_max [BB*HWSZ];              // spatial-attn max map
__device__ float  g_sw [BB*HWSZ];               // spatial-attn sigmoid map

__device__ __forceinline__ float bn_scale(float g) {
    return g * rsqrtf(1.0f + 1e-5f);
}
__device__ __forceinline__ float sigmoidf_(float v) {
    return 1.0f / (1.0f + __expf(-v));
}

// ---------------- K1: global average pool of x -> g_p ----------------
__global__ void k_pool(const float* __restrict__ x) {
    int b = blockIdx.x >> 7;
    int c = blockIdx.x & 127;
    const float* p = x + ((size_t)b * IC + c) * HWSZ;
    float s = 0.0f;
    for (int i = threadIdx.x; i < HWSZ; i += 256) s += p[i];
    __shared__ float sm[256];
    sm[threadIdx.x] = s;
    __syncthreads();
    for (int st = 128; st > 0; st >>= 1) {
        if (threadIdx.x < st) sm[threadIdx.x] += sm[threadIdx.x + st];
        __syncthreads();
    }
    if (threadIdx.x == 0) g_p[b * IC + c] = sm[0] * (1.0f / HWSZ);
}

// ---------------- K2: routing MLP + softmax (1 block) ----------------
__global__ void k_route(const float* __restrict__ rw1, const float* __restrict__ g1, const float* __restrict__ b1,
                        const float* __restrict__ rw2, const float* __restrict__ g2, const float* __restrict__ b2,
                        const float* __restrict__ rw3, const float* __restrict__ rb3) {
    __shared__ float sp[BB*IC];
    __shared__ float sh[BB*EE];
    __shared__ float sg[BB*IC];
    __shared__ float sl[BB*EE];
    int t = threadIdx.x;
    for (int i = t; i < BB*IC; i += 256) sp[i] = g_p[i];
    for (int i = t; i < BB*OC; i += 256) g_cp[i] = 0.0f;   // zero SE accumulators
    __syncthreads();
    {
        int b = t >> 4, j = t & 15;
        float a = 0.0f;
        for (int i = 0; i < IC; i++) a += sp[b*IC + i] * rw1[j*IC + i];
        a = a * bn_scale(g1[j]) + b1[j];
        sh[t] = fmaxf(a, 0.0f);
    }
    __syncthreads();
    for (int k = 0; k < 8; k++) {
        int idx = t + k*256;
        int b = idx >> 7, i = idx & 127;
        float a = 0.0f;
        for (int j = 0; j < EE; j++) a += sh[b*EE + j] * rw2[i*EE + j];
        a = a * bn_scale(g2[i]) + b2[i];
        sg[idx] = sigmoidf_(a);
    }
    __syncthreads();
    {
        int b = t >> 4, e = t & 15;
        float a = rb3[e];
        for (int i = 0; i < IC; i++) a += sg[b*IC + i] * rw3[e*IC + i];
        sl[t] = a;
    }
    __syncthreads();
    {
        int b = t >> 4;
        float m = -1e30f;
        for (int k = 0; k < EE; k++) m = fmaxf(m, sl[b*EE + k]);
        float s = 0.0f;
        for (int k = 0; k < EE; k++) s += __expf(sl[b*EE + k] - m);
        g_rw[t] = __expf(sl[t] - m) / s;
    }
}

// ---------------- K3: expert-weighted kernel generation (fp16 fragment layout) ----------------
// Per-b half layout: [chunk(4)][tap(9)][kk(2)][m(4)][lane(32)][mf(2)][j(8)]  = OIK halfs.
// j -> reg r=j>>1, pos p=j&1:
//   o  = m*32 + mf*16 + g + ((j>>1)&1)*8
//   ic = chunk*32 + kk*16 + ((j>>2)&1)*8 + 2*t + (j&1)
// with g = lane>>2, t = lane&3.
__global__ void k_wgen(const float* __restrict__ experts) {
    __shared__ float srw[BB*EE];
    int tid = threadIdx.x;
    srw[tid] = g_rw[tid];
    __syncthreads();
    int flat = blockIdx.x * 256 + tid;       // 0 .. 147455
    int chunk = flat / 36864;
    int r = flat - chunk * 36864;
    int tap = r >> 12;
    int r2 = r & 4095;
    int kk   = r2 >> 11;
    int m    = (r2 >> 9) & 3;
    int lane = (r2 >> 4) & 31;
    int mf   = (r2 >> 3) & 1;
    int j    = r2 & 7;
    int g = lane >> 2, t = lane & 3;
    int o  = m*32 + mf*16 + g + ((j >> 1) & 1)*8;
    int ic = chunk*32 + kk*16 + ((j >> 2) & 1)*8 + 2*t + (j & 1);

    const float* es = experts + ((size_t)o * IC + ic) * KK + tap;
    float acc[BB];
#pragma unroll
    for (int b2 = 0; b2 < BB; b2++) acc[b2] = 0.0f;
    for (int e = 0; e < EE; e++) {
        float ev = es[(size_t)e * OIK];
#pragma unroll
        for (int b2 = 0; b2 < BB; b2++) acc[b2] += srw[b2*EE + e] * ev;
    }
#pragma unroll
    for (int b2 = 0; b2 < BB; b2++) {
        g_wh[(size_t)b2 * OIK + flat] = __float2half_rn(acc[b2]);
    }
}

// ---------------- K4: per-sample 3x3 conv via mma.sync fp16 implicit GEMM ----------------
// CTA = (b, row h). M=128 (o) x N=128 (px) x K=1152. 8 warps 4(M)x2(N), warp tile 32x64.
// A fragments: direct LDG.128 from g_wh (fragment layout). B: half in smem, ic-stride 40
// (bank pattern 20g+t mod 32 = full permutation -> conflict-free half2 fragment loads).
#define XS_ICS 40                      // halfs per (r,c) cell (32 used + 8 pad)
#define XS_CW  130
#define XS_HALFS (3*XS_CW*XS_ICS)      // 15600 halfs
#define CONV_SMEM (XS_HALFS*2)         // 31200 bytes

#define MMA_F16(dd, Av, B0, B1) \
    asm volatile("mma.sync.aligned.m16n8k16.row.col.f32.f16.f16.f32 " \
                 "{%0,%1,%2,%3}, {%4,%5,%6,%7}, {%8,%9}, {%0,%1,%2,%3};" \
                 : "+f"((dd)[0]), "+f"((dd)[1]), "+f"((dd)[2]), "+f"((dd)[3]) \
                 : "r"((Av).x), "r"((Av).y), "r"((Av).z), "r"((Av).w), \
                   "r"(B0), "r"(B1))

__global__ void __launch_bounds__(256, 2) k_conv_mma(const float* __restrict__ x) {
    extern __shared__ __half xsh[];    // [3 r][130 c][40 ic-halfs]

    int tid  = threadIdx.x;
    int lane = tid & 31, wid = tid >> 5;
    int g = lane >> 2, t = lane & 3;
    int m4 = wid & 3;
    int om0 = m4 * 32;
    int pn0 = (wid >> 2) * 64;
    int b = blockIdx.x >> 7;
    int h = blockIdx.x & 127;

    const float* xb = x + (size_t)b * IC * HWSZ;
    const __half* wbase = g_wh + (size_t)b * OIK;

    float d[2][8][4];
#pragma unroll
    for (int mf = 0; mf < 2; mf++)
#pragma unroll
        for (int nf = 0; nf < 8; nf++)
#pragma unroll
            for (int r = 0; r < 4; r++) d[mf][nf][r] = 0.0f;

    // per-thread B base: col = pn0 + g, ic offset 2t
    const __half* bwp = xsh + (pn0 + g) * XS_ICS + 2 * t;

    for (int chunk = 0; chunk < 4; chunk++) {
        __syncthreads();               // all warps done reading xsh
        // ---- stage x rows h-1..h+1 for this 32-ic chunk (fp16) ----
        const float* xc = xb + (size_t)chunk * 32 * HWSZ;
        for (int idx = tid; idx < 32*390; idx += 256) {
            int icc = idx / 390;
            int rem = idx - icc * 390;
            int r = rem / 130, c = rem - r * 130;
            int hin = h - 1 + r, win = c - 1;
            float v = 0.0f;
            if ((unsigned)hin < 128u && (unsigned)win < 128u)
                v = xc[(size_t)icc * HWSZ + hin * WW + win];
            xsh[(r * XS_CW + c) * XS_ICS + icc] = __float2half_rn(v);
        }
        __syncthreads();

        // A fragment pointer for this (b, chunk), in halfs
        const __half* ap = wbase + (size_t)chunk * 36864 + m4 * 512 + lane * 16;

#pragma unroll
        for (int tap = 0; tap < 9; tap++) {
            const int ky = tap / 3, kx = tap - ky * 3;
            // load A fragments for this tap: [kk][mf], one LDG.128 each
            uint4 Af[2][2];
            const __half* at = ap + tap * 4096;
#pragma unroll
            for (int kk = 0; kk < 2; kk++) {
#pragma unroll
                for (int mf = 0; mf < 2; mf++)
                    Af[kk][mf] = *(const uint4*)(at + kk * 2048 + mf * 8);
            }
            const __half* bt = bwp + (ky * XS_CW + kx) * XS_ICS;
#pragma unroll
            for (int kk = 0; kk < 2; kk++) {
                const __half* bp = bt + kk * 16;
#pragma unroll
                for (int nf = 0; nf < 8; nf++) {
                    uint32_t b0 = *(const uint32_t*)(bp + nf * 8 * XS_ICS);
                    uint32_t b1 = *(const uint32_t*)(bp + nf * 8 * XS_ICS + 8);
                    MMA_F16(d[0][nf], Af[kk][0], b0, b1);
                    MMA_F16(d[1][nf], Af[kk][1], b0, b1);
                }
            }
        }
    }

    // ---- epilogue: store + fused SE channel sums ----
    float* ob = g_out + (size_t)b * OC * HWSZ + h * WW;
#pragma unroll
    for (int mf = 0; mf < 2; mf++) {
        int o0 = om0 + mf * 16 + g;
        float s0 = 0.0f, s1 = 0.0f;
#pragma unroll
        for (int nf = 0; nf < 8; nf++) {
            int px = pn0 + nf * 8 + t * 2;
            float2 v0 = make_float2(d[mf][nf][0], d[mf][nf][1]);
            float2 v1 = make_float2(d[mf][nf][2], d[mf][nf][3]);
            *(float2*)(ob + (size_t)o0 * HWSZ + px)       = v0;
            *(float2*)(ob + (size_t)(o0 + 8) * HWSZ + px) = v1;
            s0 += v0.x + v0.y;
            s1 += v1.x + v1.y;
        }
        s0 += __shfl_xor_sync(0xffffffffu, s0, 1);
        s0 += __shfl_xor_sync(0xffffffffu, s0, 2);
        s1 += __shfl_xor_sync(0xffffffffu, s1, 1);
        s1 += __shfl_xor_sync(0xffffffffu, s1, 2);
        if (t == 0) {
            atomicAdd(&g_cp[b * OC + o0], s0);
            atomicAdd(&g_cp[b * OC + o0 + 8], s1);
        }
    }
}

// ---------------- K5: SE channel attention MLP (1 block) ----------------
__global__ void k_chattn(const float* __restrict__ w1, const float* __restrict__ g1, const float* __restrict__ b1,
                         const float* __restrict__ w2, const float* __restrict__ g2, const float* __restrict__ b2) {
    __shared__ float scp[BB*OC];
    __shared__ float sh[BB*16];
    int t = threadIdx.x;
    for (int i = t; i < BB*OC; i += 256) scp[i] = g_cp[i] * (1.0f / HWSZ);
    __syncthreads();
    {
        int b = t >> 4, j = t & 15;
        float a = 0.0f;
        for (int i = 0; i < OC; i++) a += scp[b*OC + i] * w1[j*OC + i];
        a = a * bn_scale(g1[j]) + b1[j];
        sh[t] = fmaxf(a, 0.0f);
    }
    __syncthreads();
    for (int k = 0; k < 8; k++) {
        int idx = t + k*256;
        int b = idx >> 7, i = idx & 127;
        float a = 0.0f;
        for (int j = 0; j < 16; j++) a += sh[b*16 + j] * w2[i*16 + j];
        a = a * bn_scale(g2[i]) + b2[i];
        g_cw[idx] = sigmoidf_(a);
    }
}

// ---------------- K6: spatial mean/max over channels of out*cw ----------------
__global__ void k_spstats() {
    __shared__ float scw[OC];
    int blk = blockIdx.x;
    int b = blk >> 6;
    int t = threadIdx.x;
    if (t < OC) scw[t] = g_cw[b*OC + t];
    __syncthreads();
    int hw = (blk & 63) * 256 + t;
    const float* ob = g_out + (size_t)b * OC * HWSZ + hw;
    float s = 0.0f, m = -1e30f;
    for (int o = 0; o < OC; o++) {
        float v = ob[(size_t)o * HWSZ] * scw[o];
        s += v;
        m = fmaxf(m, v);
    }
    g_mean[b*HWSZ + hw] = s * (1.0f / OC);
    g_max [b*HWSZ + hw] = m;
}

// ---------------- K7: 7x7 spatial-attention conv + sigmoid(bn) ----------------
__global__ void k_spconv(const float* __restrict__ saw, const float* __restrict__ sg, const float* __restrict__ sb) {
    __shared__ float sw_[98];
    int t = threadIdx.x;
    if (t < 98) sw_[t] = saw[t];
    __syncthreads();
    int idx = blockIdx.x * 256 + t;
    int b = idx >> 14;
    int hw = idx & 16383;
    int h = hw >> 7, w = hw & 127;
    float a = 0.0f;
    const float* mb = g_mean + (size_t)b * HWSZ;
    const float* xb = g_max  + (size_t)b * HWSZ;
    for (int kh = 0; kh < 7; kh++) {
        int hh = h + kh - 3;
        if (hh < 0 || hh >= HH) continue;
        for (int kw = 0; kw < 7; kw++) {
            int ww = w + kw - 3;
            if (ww < 0 || ww >= WW) continue;
            int o = hh*WW + ww;
            a += mb[o] * sw_[kh*7 + kw] + xb[o] * sw_[49 + kh*7 + kw];
        }
    }
    a = a * bn_scale(sg[0]) + sb[0];
    g_sw[idx] = sigmoidf_(a);
}

// ---------------- K8: final out = conv*cw*sw + x ----------------
__global__ void k_final(const float* __restrict__ x, float* __restrict__ out) {
    size_t i4 = (size_t)blockIdx.x * 256 + threadIdx.x;
    size_t e = i4 * 4;
    int b  = (int)(e >> 21);
    int o  = (int)((e >> 14) & 127);
    int hw = (int)(e & 16383);
    float cw = g_cw[b*OC + o];
    float4 v  = *(const float4*)(g_out + e);
    float4 xv = ((const float4*)x)[i4];
    float4 sv = *(const float4*)(g_sw + (size_t)b*HWSZ + hw);
    float4 r;
    r.x = v.x * cw * sv.x + xv.x;
    r.y = v.y * cw * sv.y + xv.y;
    r.z = v.z * cw * sv.z + xv.z;
    r.w = v.w * cw * sv.w + xv.w;
    ((float4*)out)[i4] = r;
}

// ---------------- launcher ----------------
extern "C" void kernel_launch(void* const* d_in, const int* in_sizes, int n_in,
                              void* d_out, int out_size) {
    const float* x        = (const float*)d_in[0];
    const float* experts  = (const float*)d_in[1];
    const float* rw1      = (const float*)d_in[2];
    const float* rbn1_g   = (const float*)d_in[3];
    const float* rbn1_b   = (const float*)d_in[4];
    const float* rw2      = (const float*)d_in[5];
    const float* rbn2_g   = (const float*)d_in[6];
    const float* rbn2_b   = (const float*)d_in[7];
    const float* rw3      = (const float*)d_in[8];
    const float* rb3      = (const float*)d_in[9];
    const float* ca_w1    = (const float*)d_in[10];
    const float* ca_bn1_g = (const float*)d_in[11];
    const float* ca_bn1_b = (const float*)d_in[12];
    const float* ca_w2    = (const float*)d_in[13];
    const float* ca_bn2_g = (const float*)d_in[14];
    const float* ca_bn2_b = (const float*)d_in[15];
    const float* sa_w     = (const float*)d_in[16];
    const float* sa_bn_g  = (const float*)d_in[17];
    const float* sa_bn_b  = (const float*)d_in[18];
    float* out = (float*)d_out;

    k_pool<<<BB*IC, 256>>>(x);
    k_route<<<1, 256>>>(rw1, rbn1_g, rbn1_b, rw2, rbn2_g, rbn2_b, rw3, rb3);
    k_wgen<<<OIK/256, 256>>>(experts);
    k_conv_mma<<<BB*HH, 256, CONV_SMEM>>>(x);
    k_chattn<<<1, 256>>>(ca_w1, ca_bn1_g, ca_bn1_b, ca_w2, ca_bn2_g, ca_bn2_b);
    k_spstats<<<BB*64, 256>>>();
    k_spconv<<<BB*64, 256>>>(sa_w, sa_bn_g, sa_bn_b);
    k_final<<<(BB*OC*HWSZ)/(4*256), 256>>>(x, out);
}

// round 15
// speedup vs baseline: 6.9918x; 1.0907x over previous
#include <cuda_runtime.h>
#include <cuda_fp16.h>
#include <math.h>
#include <stdint.h>

// Problem constants (fixed shapes)
#define BB   16
#define IC   128
#define OC   128
#define HH   128
#define WW   128
#define EE   16
#define HWSZ (HH*WW)            // 16384
#define KK   9
#define OIK  (OC*IC*KK)         // 147456

// ---------------- device scratch (static, no runtime alloc) ----------------
__device__ float  g_p  [BB*IC];                 // pooled x
__device__ float  g_rw [BB*EE];                 // routing weights (softmax)
__device__ __half g_wh [(size_t)BB*OIK];        // per-sample weights, fp16 fragment layout (4.7 MB)
__device__ float  g_out[(size_t)BB*OC*HWSZ];    // conv output              (134 MB)
__device__ float  g_cp [BB*OC];                 // per-(b,o) sums for SE
__device__ float  g_cw [BB*OC];                 // SE channel weights
__device__ float  g_mean[BB*HWSZ];              // spatial-attn mean map
__device__ float  g_max [BB*HWSZ];              // spatial-attn max map
__device__ float  g_sw [BB*HWSZ];               // spatial-attn sigmoid map

__device__ __forceinline__ float bn_scale(float g) {
    return g * rsqrtf(1.0f + 1e-5f);
}
__device__ __forceinline__ float sigmoidf_(float v) {
    return 1.0f / (1.0f + __expf(-v));
}

// ---------------- K1: global average pool of x -> g_p ----------------
__global__ void k_pool(const float* __restrict__ x) {
    int b = blockIdx.x >> 7;
    int c = blockIdx.x & 127;
    const float* p = x + ((size_t)b * IC + c) * HWSZ;
    float s = 0.0f;
    for (int i = threadIdx.x; i < HWSZ; i += 256) s += p[i];
    __shared__ float sm[256];
    sm[threadIdx.x] = s;
    __syncthreads();
    for (int st = 128; st > 0; st >>= 1) {
        if (threadIdx.x < st) sm[threadIdx.x] += sm[threadIdx.x + st];
        __syncthreads();
    }
    if (threadIdx.x == 0) g_p[b * IC + c] = sm[0] * (1.0f / HWSZ);
}

// ---------------- K2: routing MLP + softmax (1 block) ----------------
__global__ void k_route(const float* __restrict__ rw1, const float* __restrict__ g1, const float* __restrict__ b1,
                        const float* __restrict__ rw2, const float* __restrict__ g2, const float* __restrict__ b2,
                        const float* __restrict__ rw3, const float* __restrict__ rb3) {
    __shared__ float sp[BB*IC];
    __shared__ float sh[BB*EE];
    __shared__ float sg[BB*IC];
    __shared__ float sl[BB*EE];
    int t = threadIdx.x;
    for (int i = t; i < BB*IC; i += 256) sp[i] = g_p[i];
    for (int i = t; i < BB*OC; i += 256) g_cp[i] = 0.0f;   // zero SE accumulators
    __syncthreads();
    {
        int b = t >> 4, j = t & 15;
        float a = 0.0f;
        for (int i = 0; i < IC; i++) a += sp[b*IC + i] * rw1[j*IC + i];
        a = a * bn_scale(g1[j]) + b1[j];
        sh[t] = fmaxf(a, 0.0f);
    }
    __syncthreads();
    for (int k = 0; k < 8; k++) {
        int idx = t + k*256;
        int b = idx >> 7, i = idx & 127;
        float a = 0.0f;
        for (int j = 0; j < EE; j++) a += sh[b*EE + j] * rw2[i*EE + j];
        a = a * bn_scale(g2[i]) + b2[i];
        sg[idx] = sigmoidf_(a);
    }
    __syncthreads();
    {
        int b = t >> 4, e = t & 15;
        float a = rb3[e];
        for (int i = 0; i < IC; i++) a += sg[b*IC + i] * rw3[e*IC + i];
        sl[t] = a;
    }
    __syncthreads();
    {
        int b = t >> 4;
        float m = -1e30f;
        for (int k = 0; k < EE; k++) m = fmaxf(m, sl[b*EE + k]);
        float s = 0.0f;
        for (int k = 0; k < EE; k++) s += __expf(sl[b*EE + k] - m);
        g_rw[t] = __expf(sl[t] - m) / s;
    }
}

// ---------------- K3: expert-weighted kernel generation (fp16 fragment layout) ----------------
// Per-b half layout: [chunk(4)][tap(9)][kk(2)][m(4)][mf(2)][lane(32)][j(8)]  = OIK halfs.
//   o  = m*32 + mf*16 + g + ((j>>1)&1)*8
//   ic = chunk*32 + kk*16 + ((j>>2)&1)*8 + 2*t + (j&1)
// with g = lane>>2, t = lane&3.
__global__ void k_wgen(const float* __restrict__ experts) {
    __shared__ float srw[BB*EE];
    int tid = threadIdx.x;
    srw[tid] = g_rw[tid];
    __syncthreads();
    int flat = blockIdx.x * 256 + tid;       // 0 .. 147455
    int chunk = flat / 36864;
    int r = flat - chunk * 36864;
    int tap = r >> 12;
    int r2 = r & 4095;
    int kk   = r2 >> 11;
    int m    = (r2 >> 9) & 3;
    int mf   = (r2 >> 8) & 1;
    int lane = (r2 >> 3) & 31;
    int j    = r2 & 7;
    int g = lane >> 2, t = lane & 3;
    int o  = m*32 + mf*16 + g + ((j >> 1) & 1)*8;
    int ic = chunk*32 + kk*16 + ((j >> 2) & 1)*8 + 2*t + (j & 1);

    const float* es = experts + ((size_t)o * IC + ic) * KK + tap;
    float acc[BB];
#pragma unroll
    for (int b2 = 0; b2 < BB; b2++) acc[b2] = 0.0f;
    for (int e = 0; e < EE; e++) {
        float ev = es[(size_t)e * OIK];
#pragma unroll
        for (int b2 = 0; b2 < BB; b2++) acc[b2] += srw[b2*EE + e] * ev;
    }
#pragma unroll
    for (int b2 = 0; b2 < BB; b2++) {
        g_wh[(size_t)b2 * OIK + flat] = __float2half_rn(acc[b2]);
    }
}

// ---------------- K4: per-sample 3x3 conv via mma.sync fp16 implicit GEMM ----------------
// CTA = (b, row h). M=128 (o) x N=128 (px) x K=1152. 8 warps 4(M)x2(N), warp tile 32x64.
// A: per-chunk cp.async gmem->smem (72 KB, fragment layout), inner-loop LDS.128 conflict-free.
// B: half in smem, cell stride 40 halfs (conflict-free fragment LDS.32).
#define XS_ICS 40                      // halfs per (r,c) cell (32 used + 8 pad)
#define XS_CW  130
#define XS_HALFS (3*XS_CW*XS_ICS)      // 15600 halfs = 31200 B
#define A_HALFS  36864                 // per-chunk A block (73728 B)
#define CONV_SMEM ((XS_HALFS + A_HALFS)*2)   // 104928 bytes

#define CPA16(dst, src) asm volatile("cp.async.ca.shared.global [%0], [%1], 16;" :: "r"(dst), "l"(src) : "memory")
#define CPC()           asm volatile("cp.async.commit_group;" ::: "memory")
#define CPW0()          asm volatile("cp.async.wait_group 0;" ::: "memory")

#define MMA_F16(dd, Av, B0, B1) \
    asm volatile("mma.sync.aligned.m16n8k16.row.col.f32.f16.f16.f32 " \
                 "{%0,%1,%2,%3}, {%4,%5,%6,%7}, {%8,%9}, {%0,%1,%2,%3};" \
                 : "+f"((dd)[0]), "+f"((dd)[1]), "+f"((dd)[2]), "+f"((dd)[3]) \
                 : "r"((Av).x), "r"((Av).y), "r"((Av).z), "r"((Av).w), \
                   "r"(B0), "r"(B1))

__global__ void __launch_bounds__(256, 2) k_conv_mma(const float* __restrict__ x) {
    extern __shared__ __half xsh[];    // [3 r][130 c][40 ic-halfs] then A block [36864]
    __half* Ash = xsh + XS_HALFS;
    uint32_t a_dst = (uint32_t)__cvta_generic_to_shared(Ash);

    int tid  = threadIdx.x;
    int lane = tid & 31, wid = tid >> 5;
    int g = lane >> 2, t = lane & 3;
    int m4 = wid & 3;
    int om0 = m4 * 32;
    int pn0 = (wid >> 2) * 64;
    int b = blockIdx.x >> 7;
    int h = blockIdx.x & 127;

    const float* xb = x + (size_t)b * IC * HWSZ;
    const __half* wbase = g_wh + (size_t)b * OIK;

    float d[2][8][4];
#pragma unroll
    for (int mf = 0; mf < 2; mf++)
#pragma unroll
        for (int nf = 0; nf < 8; nf++)
#pragma unroll
            for (int r = 0; r < 4; r++) d[mf][nf][r] = 0.0f;

    // per-thread bases
    const __half* bwp = xsh + (pn0 + g) * XS_ICS + 2 * t;       // B fragments
    const __half* awp = Ash + m4 * 512 + lane * 8;              // A fragments (halfs)

    for (int chunk = 0; chunk < 4; chunk++) {
        __syncthreads();               // all warps done reading xsh/Ash
        // ---- kick off A block copy for this chunk (72 KB, linear, coalesced) ----
        {
            const char* asrc = (const char*)(wbase + (size_t)chunk * A_HALFS);
#pragma unroll
            for (int it = 0; it < 18; it++) {
                int off = (it * 256 + tid) * 16;
                CPA16(a_dst + off, asrc + off);
            }
            CPC();
        }
        // ---- stage x rows h-1..h+1 for this 32-ic chunk (fp16, division-free) ----
        const float* xc = xb + (size_t)chunk * 32 * HWSZ;
        for (int pr = wid; pr < 96; pr += 8) {       // pr = r*32 + icc
            int r = pr >> 5, icc = pr & 31;
            int hin = h - 1 + r;
            bool rowok = (unsigned)hin < 128u;
            const float* xr = xc + (size_t)icc * HWSZ + hin * WW;
            __half* drow = xsh + r * (XS_CW * XS_ICS) + icc;
#pragma unroll
            for (int c5 = 0; c5 < 5; c5++) {
                int c = lane + c5 * 32;
                if (c < 130) {
                    int win = c - 1;
                    float v = (rowok && (unsigned)win < 128u) ? xr[win] : 0.0f;
                    drow[c * XS_ICS] = __float2half_rn(v);
                }
            }
        }
        CPW0();
        __syncthreads();

#pragma unroll
        for (int tap = 0; tap < 9; tap++) {
            const int ky = tap / 3, kx = tap - ky * 3;
            // A fragments for this tap: [kk][mf], conflict-free LDS.128 (imm offsets)
            uint4 Af[2][2];
#pragma unroll
            for (int kk = 0; kk < 2; kk++) {
#pragma unroll
                for (int mf = 0; mf < 2; mf++)
                    Af[kk][mf] = *(const uint4*)(awp + tap * 4096 + kk * 2048 + mf * 256);
            }
            const __half* bt = bwp + (ky * XS_CW + kx) * XS_ICS;
#pragma unroll
            for (int kk = 0; kk < 2; kk++) {
                const __half* bp = bt + kk * 16;
#pragma unroll
                for (int nf = 0; nf < 8; nf++) {
                    uint32_t b0 = *(const uint32_t*)(bp + nf * 8 * XS_ICS);
                    uint32_t b1 = *(const uint32_t*)(bp + nf * 8 * XS_ICS + 8);
                    MMA_F16(d[0][nf], Af[kk][0], b0, b1);
                    MMA_F16(d[1][nf], Af[kk][1], b0, b1);
                }
            }
        }
    }

    // ---- epilogue: store + fused SE channel sums ----
    float* ob = g_out + (size_t)b * OC * HWSZ + h * WW;
#pragma unroll
    for (int mf = 0; mf < 2; mf++) {
        int o0 = om0 + mf * 16 + g;
        float s0 = 0.0f, s1 = 0.0f;
#pragma unroll
        for (int nf = 0; nf < 8; nf++) {
            int px = pn0 + nf * 8 + t * 2;
            float2 v0 = make_float2(d[mf][nf][0], d[mf][nf][1]);
            float2 v1 = make_float2(d[mf][nf][2], d[mf][nf][3]);
            *(float2*)(ob + (size_t)o0 * HWSZ + px)       = v0;
            *(float2*)(ob + (size_t)(o0 + 8) * HWSZ + px) = v1;
            s0 += v0.x + v0.y;
            s1 += v1.x + v1.y;
        }
        s0 += __shfl_xor_sync(0xffffffffu, s0, 1);
        s0 += __shfl_xor_sync(0xffffffffu, s0, 2);
        s1 += __shfl_xor_sync(0xffffffffu, s1, 1);
        s1 += __shfl_xor_sync(0xffffffffu, s1, 2);
        if (t == 0) {
            atomicAdd(&g_cp[b * OC + o0], s0);
            atomicAdd(&g_cp[b * OC + o0 + 8], s1);
        }
    }
}

// ---------------- K5: SE channel attention MLP (1 block) ----------------
__global__ void k_chattn(const float* __restrict__ w1, const float* __restrict__ g1, const float* __restrict__ b1,
                         const float* __restrict__ w2, const float* __restrict__ g2, const float* __restrict__ b2) {
    __shared__ float scp[BB*OC];
    __shared__ float sh[BB*16];
    int t = threadIdx.x;
    for (int i = t; i < BB*OC; i += 256) scp[i] = g_cp[i] * (1.0f / HWSZ);
    __syncthreads();
    {
        int b = t >> 4, j = t & 15;
        float a = 0.0f;
        for (int i = 0; i < OC; i++) a += scp[b*OC + i] * w1[j*OC + i];
        a = a * bn_scale(g1[j]) + b1[j];
        sh[t] = fmaxf(a, 0.0f);
    }
    __syncthreads();
    for (int k = 0; k < 8; k++) {
        int idx = t + k*256;
        int b = idx >> 7, i = idx & 127;
        float a = 0.0f;
        for (int j = 0; j < 16; j++) a += sh[b*16 + j] * w2[i*16 + j];
        a = a * bn_scale(g2[i]) + b2[i];
        g_cw[idx] = sigmoidf_(a);
    }
}

// ---------------- K6: spatial mean/max over channels of out*cw ----------------
__global__ void k_spstats() {
    __shared__ float scw[OC];
    int blk = blockIdx.x;
    int b = blk >> 6;
    int t = threadIdx.x;
    if (t < OC) scw[t] = g_cw[b*OC + t];
    __syncthreads();
    int hw = (blk & 63) * 256 + t;
    const float* ob = g_out + (size_t)b * OC * HWSZ + hw;
    float s = 0.0f, m = -1e30f;
    for (int o = 0; o < OC; o++) {
        float v = ob[(size_t)o * HWSZ] * scw[o];
        s += v;
        m = fmaxf(m, v);
    }
    g_mean[b*HWSZ + hw] = s * (1.0f / OC);
    g_max [b*HWSZ + hw] = m;
}

// ---------------- K7: 7x7 spatial-attention conv + sigmoid(bn) ----------------
__global__ void k_spconv(const float* __restrict__ saw, const float* __restrict__ sg, const float* __restrict__ sb) {
    __shared__ float sw_[98];
    int t = threadIdx.x;
    if (t < 98) sw_[t] = saw[t];
    __syncthreads();
    int idx = blockIdx.x * 256 + t;
    int b = idx >> 14;
    int hw = idx & 16383;
    int h = hw >> 7, w = hw & 127;
    float a = 0.0f;
    const float* mb = g_mean + (size_t)b * HWSZ;
    const float* xb = g_max  + (size_t)b * HWSZ;
    for (int kh = 0; kh < 7; kh++) {
        int hh = h + kh - 3;
        if (hh < 0 || hh >= HH) continue;
        for (int kw = 0; kw < 7; kw++) {
            int ww = w + kw - 3;
            if (ww < 0 || ww >= WW) continue;
            int o = hh*WW + ww;
            a += mb[o] * sw_[kh*7 + kw] + xb[o] * sw_[49 + kh*7 + kw];
        }
    }
    a = a * bn_scale(sg[0]) + sb[0];
    g_sw[idx] = sigmoidf_(a);
}

// ---------------- K8: final out = conv*cw*sw + x ----------------
__global__ void k_final(const float* __restrict__ x, float* __restrict__ out) {
    size_t i4 = (size_t)blockIdx.x * 256 + threadIdx.x;
    size_t e = i4 * 4;
    int b  = (int)(e >> 21);
    int o  = (int)((e >> 14) & 127);
    int hw = (int)(e & 16383);
    float cw = g_cw[b*OC + o];
    float4 v  = *(const float4*)(g_out + e);
    float4 xv = ((const float4*)x)[i4];
    float4 sv = *(const float4*)(g_sw + (size_t)b*HWSZ + hw);
    float4 r;
    r.x = v.x * cw * sv.x + xv.x;
    r.y = v.y * cw * sv.y + xv.y;
    r.z = v.z * cw * sv.z + xv.z;
    r.w = v.w * cw * sv.w + xv.w;
    ((float4*)out)[i4] = r;
}

// ---------------- launcher ----------------
extern "C" void kernel_launch(void* const* d_in, const int* in_sizes, int n_in,
                              void* d_out, int out_size) {
    const float* x        = (const float*)d_in[0];
    const float* experts  = (const float*)d_in[1];
    const float* rw1      = (const float*)d_in[2];
    const float* rbn1_g   = (const float*)d_in[3];
    const float* rbn1_b   = (const float*)d_in[4];
    const float* rw2      = (const float*)d_in[5];
    const float* rbn2_g   = (const float*)d_in[6];
    const float* rbn2_b   = (const float*)d_in[7];
    const float* rw3      = (const float*)d_in[8];
    const float* rb3      = (const float*)d_in[9];
    const float* ca_w1    = (const float*)d_in[10];
    const float* ca_bn1_g = (const float*)d_in[11];
    const float* ca_bn1_b = (const float*)d_in[12];
    const float* ca_w2    = (const float*)d_in[13];
    const float* ca_bn2_g = (const float*)d_in[14];
    const float* ca_bn2_b = (const float*)d_in[15];
    const float* sa_w     = (const float*)d_in[16];
    const float* sa_bn_g  = (const float*)d_in[17];
    const float* sa_bn_b  = (const float*)d_in[18];
    float* out = (float*)d_out;

    cudaFuncSetAttribute(k_conv_mma, cudaFuncAttributeMaxDynamicSharedMemorySize, CONV_SMEM);

    k_pool<<<BB*IC, 256>>>(x);
    k_route<<<1, 256>>>(rw1, rbn1_g, rbn1_b, rw2, rbn2_g, rbn2_b, rw3, rb3);
    k_wgen<<<OIK/256, 256>>>(experts);
    k_conv_mma<<<BB*HH, 256, CONV_SMEM>>>(x);
    k_chattn<<<1, 256>>>(ca_w1, ca_bn1_g, ca_bn1_b, ca_w2, ca_bn2_g, ca_bn2_b);
    k_spstats<<<BB*64, 256>>>();
    k_spconv<<<BB*64, 256>>>(sa_w, sa_bn_g, sa_bn_b);
    k_final<<<(BB*OC*HWSZ)/(4*256), 256>>>(x, out);
}

// round 16
// speedup vs baseline: 7.1138x; 1.0175x over previous
#include <cuda_runtime.h>
#include <cuda_fp16.h>
#include <math.h>
#include <stdint.h>

// Problem constants (fixed shapes)
#define BB   16
#define IC   128
#define OC   128
#define HH   128
#define WW   128
#define EE   16
#define HWSZ (HH*WW)            // 16384
#define KK   9
#define OIK  (OC*IC*KK)         // 147456

// ---------------- device scratch (static, no runtime alloc) ----------------
__device__ float  g_p  [BB*IC];                 // pooled x
__device__ float  g_rw [BB*EE];                 // routing weights (softmax)
__device__ __half g_wh [(size_t)BB*OIK];        // per-sample weights, fp16 fragment layout (4.7 MB)
__device__ float  g_out[(size_t)BB*OC*HWSZ];    // conv output              (134 MB)
__device__ float  g_cp [BB*OC];                 // per-(b,o) sums for SE
__device__ float  g_cw [BB*OC];                 // SE channel weights
__device__ float  g_mean[BB*HWSZ];              // spatial-attn mean map
__device__ float  g_max [BB*HWSZ];              // spatial-attn max map
__device__ float  g_sw [BB*HWSZ];               // spatial-attn sigmoid map

__device__ __forceinline__ float bn_scale(float g) {
    return g * rsqrtf(1.0f + 1e-5f);
}
__device__ __forceinline__ float sigmoidf_(float v) {
    return 1.0f / (1.0f + __expf(-v));
}

// ---------------- K1: global average pool of x -> g_p ----------------
__global__ void k_pool(const float* __restrict__ x) {
    int b = blockIdx.x >> 7;
    int c = blockIdx.x & 127;
    const float* p = x + ((size_t)b * IC + c) * HWSZ;
    float s = 0.0f;
    for (int i = threadIdx.x; i < HWSZ; i += 256) s += p[i];
    __shared__ float sm[256];
    sm[threadIdx.x] = s;
    __syncthreads();
    for (int st = 128; st > 0; st >>= 1) {
        if (threadIdx.x < st) sm[threadIdx.x] += sm[threadIdx.x + st];
        __syncthreads();
    }
    if (threadIdx.x == 0) g_p[b * IC + c] = sm[0] * (1.0f / HWSZ);
}

// ---------------- K2: routing MLP + softmax (1 block) ----------------
__global__ void k_route(const float* __restrict__ rw1, const float* __restrict__ g1, const float* __restrict__ b1,
                        const float* __restrict__ rw2, const float* __restrict__ g2, const float* __restrict__ b2,
                        const float* __restrict__ rw3, const float* __restrict__ rb3) {
    __shared__ float sp[BB*IC];
    __shared__ float sh[BB*EE];
    __shared__ float sg[BB*IC];
    __shared__ float sl[BB*EE];
    int t = threadIdx.x;
    for (int i = t; i < BB*IC; i += 256) sp[i] = g_p[i];
    for (int i = t; i < BB*OC; i += 256) g_cp[i] = 0.0f;   // zero SE accumulators
    __syncthreads();
    {
        int b = t >> 4, j = t & 15;
        float a = 0.0f;
        for (int i = 0; i < IC; i++) a += sp[b*IC + i] * rw1[j*IC + i];
        a = a * bn_scale(g1[j]) + b1[j];
        sh[t] = fmaxf(a, 0.0f);
    }
    __syncthreads();
    for (int k = 0; k < 8; k++) {
        int idx = t + k*256;
        int b = idx >> 7, i = idx & 127;
        float a = 0.0f;
        for (int j = 0; j < EE; j++) a += sh[b*EE + j] * rw2[i*EE + j];
        a = a * bn_scale(g2[i]) + b2[i];
        sg[idx] = sigmoidf_(a);
    }
    __syncthreads();
    {
        int b = t >> 4, e = t & 15;
        float a = rb3[e];
        for (int i = 0; i < IC; i++) a += sg[b*IC + i] * rw3[e*IC + i];
        sl[t] = a;
    }
    __syncthreads();
    {
        int b = t >> 4;
        float m = -1e30f;
        for (int k = 0; k < EE; k++) m = fmaxf(m, sl[b*EE + k]);
        float s = 0.0f;
        for (int k = 0; k < EE; k++) s += __expf(sl[b*EE + k] - m);
        g_rw[t] = __expf(sl[t] - m) / s;
    }
}

// ---------------- K3: expert-weighted kernel generation (fp16 fragment layout) ----------------
// Per-b half layout: [chunk(4)][tap(9)][kk(2)][m(4)][mf(2)][lane(32)][j(8)]  = OIK halfs.
//   o  = m*32 + mf*16 + g + ((j>>1)&1)*8
//   ic = chunk*32 + kk*16 + ((j>>2)&1)*8 + 2*t + (j&1)
// with g = lane>>2, t = lane&3.
__global__ void k_wgen(const float* __restrict__ experts) {
    __shared__ float srw[BB*EE];
    int tid = threadIdx.x;
    srw[tid] = g_rw[tid];
    __syncthreads();
    int flat = blockIdx.x * 256 + tid;       // 0 .. 147455
    int chunk = flat / 36864;
    int r = flat - chunk * 36864;
    int tap = r >> 12;
    int r2 = r & 4095;
    int kk   = r2 >> 11;
    int m    = (r2 >> 9) & 3;
    int mf   = (r2 >> 8) & 1;
    int lane = (r2 >> 3) & 31;
    int j    = r2 & 7;
    int g = lane >> 2, t = lane & 3;
    int o  = m*32 + mf*16 + g + ((j >> 1) & 1)*8;
    int ic = chunk*32 + kk*16 + ((j >> 2) & 1)*8 + 2*t + (j & 1);

    const float* es = experts + ((size_t)o * IC + ic) * KK + tap;
    float acc[BB];
#pragma unroll
    for (int b2 = 0; b2 < BB; b2++) acc[b2] = 0.0f;
    for (int e = 0; e < EE; e++) {
        float ev = es[(size_t)e * OIK];
#pragma unroll
        for (int b2 = 0; b2 < BB; b2++) acc[b2] += srw[b2*EE + e] * ev;
    }
#pragma unroll
    for (int b2 = 0; b2 < BB; b2++) {
        g_wh[(size_t)b2 * OIK + flat] = __float2half_rn(acc[b2]);
    }
}

// ---------------- K4: per-sample 3x3 conv via mma.sync fp16 implicit GEMM ----------------
// CTA = (b, row h). M=128 (o) x N=128 (px) x K=1152. 8 warps 4(M)x2(N), warp tile 32x64.
// A: per-chunk cp.async gmem->smem (72 KB, fragment layout), inner-loop LDS.128 conflict-free.
// B: half in smem, cell stride 40 halfs; fragments via ldmatrix.m8n8.x4 (conflict-free).
#define XS_ICS 40                      // halfs per (r,c) cell (32 used + 8 pad)
#define XS_CW  130
#define XS_HALFS (3*XS_CW*XS_ICS)      // 15600 halfs = 31200 B
#define A_HALFS  36864                 // per-chunk A block (73728 B)
#define CONV_SMEM ((XS_HALFS + A_HALFS)*2)   // 104928 bytes

#define CPA16(dst, src) asm volatile("cp.async.ca.shared.global [%0], [%1], 16;" :: "r"(dst), "l"(src) : "memory")
#define CPC()           asm volatile("cp.async.commit_group;" ::: "memory")
#define CPW0()          asm volatile("cp.async.wait_group 0;" ::: "memory")

#define MMA_F16(dd, Av, B0, B1) \
    asm volatile("mma.sync.aligned.m16n8k16.row.col.f32.f16.f16.f32 " \
                 "{%0,%1,%2,%3}, {%4,%5,%6,%7}, {%8,%9}, {%0,%1,%2,%3};" \
                 : "+f"((dd)[0]), "+f"((dd)[1]), "+f"((dd)[2]), "+f"((dd)[3]) \
                 : "r"((Av).x), "r"((Av).y), "r"((Av).z), "r"((Av).w), \
                   "r"(B0), "r"(B1))

#define LDMX4(r0, r1, r2, r3, addr) \
    asm volatile("ldmatrix.sync.aligned.m8n8.x4.shared.b16 {%0,%1,%2,%3}, [%4];" \
                 : "=r"(r0), "=r"(r1), "=r"(r2), "=r"(r3) : "r"(addr))

__global__ void __launch_bounds__(256, 2) k_conv_mma(const float* __restrict__ x) {
    extern __shared__ __half xsh[];    // [3 r][130 c][40 ic-halfs] then A block [36864]
    __half* Ash = xsh + XS_HALFS;
    uint32_t a_dst  = (uint32_t)__cvta_generic_to_shared(Ash);
    uint32_t xs_u32 = (uint32_t)__cvta_generic_to_shared(xsh);

    int tid  = threadIdx.x;
    int lane = tid & 31, wid = tid >> 5;
    int g = lane >> 2, t = lane & 3;
    int m4 = wid & 3;
    int om0 = m4 * 32;
    int pn0 = (wid >> 2) * 64;
    int b = blockIdx.x >> 7;
    int h = blockIdx.x & 127;

    const float* xb = x + (size_t)b * IC * HWSZ;
    const __half* wbase = g_wh + (size_t)b * OIK;

    float d[2][8][4];
#pragma unroll
    for (int mf = 0; mf < 2; mf++)
#pragma unroll
        for (int nf = 0; nf < 8; nf++)
#pragma unroll
            for (int r = 0; r < 4; r++) d[mf][nf][r] = 0.0f;

    // per-thread bases
    // ldmatrix row address: lane l -> matrix j=l>>3 (kk=j>>1, kgroup=j&1), row r=l&7 (n offset)
    uint32_t p_lm = xs_u32 +
        (((pn0 + (lane & 7)) * XS_ICS) + ((lane >> 4) * 16) + (((lane >> 3) & 1) * 8)) * 2;
    const __half* awp = Ash + m4 * 512 + lane * 8;              // A fragments (halfs)

    for (int chunk = 0; chunk < 4; chunk++) {
        __syncthreads();               // all warps done reading xsh/Ash
        // ---- kick off A block copy for this chunk (72 KB, linear, coalesced) ----
        {
            const char* asrc = (const char*)(wbase + (size_t)chunk * A_HALFS);
#pragma unroll
            for (int it = 0; it < 18; it++) {
                int off = (it * 256 + tid) * 16;
                CPA16(a_dst + off, asrc + off);
            }
            CPC();
        }
        // ---- stage x rows h-1..h+1 for this 32-ic chunk (fp16, division-free) ----
        const float* xc = xb + (size_t)chunk * 32 * HWSZ;
        for (int pr = wid; pr < 96; pr += 8) {       // pr = r*32 + icc
            int r = pr >> 5, icc = pr & 31;
            int hin = h - 1 + r;
            bool rowok = (unsigned)hin < 128u;
            const float* xr = xc + (size_t)icc * HWSZ + hin * WW;
            __half* drow = xsh + r * (XS_CW * XS_ICS) + icc;
#pragma unroll
            for (int c5 = 0; c5 < 5; c5++) {
                int c = lane + c5 * 32;
                if (c < 130) {
                    int win = c - 1;
                    float v = (rowok && (unsigned)win < 128u) ? xr[win] : 0.0f;
                    drow[c * XS_ICS] = __float2half_rn(v);
                }
            }
        }
        CPW0();
        __syncthreads();

#pragma unroll
        for (int tap = 0; tap < 9; tap++) {
            const int ky = tap / 3, kx = tap - ky * 3;
            // A fragments for this tap: [kk][mf], conflict-free LDS.128 (imm offsets)
            uint4 Af[2][2];
#pragma unroll
            for (int kk = 0; kk < 2; kk++) {
#pragma unroll
                for (int mf = 0; mf < 2; mf++)
                    Af[kk][mf] = *(const uint4*)(awp + tap * 4096 + kk * 2048 + mf * 256);
            }
            uint32_t pt = p_lm + (ky * XS_CW + kx) * (XS_ICS * 2);
#pragma unroll
            for (int nf = 0; nf < 8; nf++) {
                uint32_t b0, b1, b2, b3;
                LDMX4(b0, b1, b2, b3, pt + nf * (8 * XS_ICS * 2));
                MMA_F16(d[0][nf], Af[0][0], b0, b1);
                MMA_F16(d[1][nf], Af[0][1], b0, b1);
                MMA_F16(d[0][nf], Af[1][0], b2, b3);
                MMA_F16(d[1][nf], Af[1][1], b2, b3);
            }
        }
    }

    // ---- epilogue: store + fused SE channel sums ----
    float* ob = g_out + (size_t)b * OC * HWSZ + h * WW;
#pragma unroll
    for (int mf = 0; mf < 2; mf++) {
        int o0 = om0 + mf * 16 + g;
        float s0 = 0.0f, s1 = 0.0f;
#pragma unroll
        for (int nf = 0; nf < 8; nf++) {
            int px = pn0 + nf * 8 + t * 2;
            float2 v0 = make_float2(d[mf][nf][0], d[mf][nf][1]);
            float2 v1 = make_float2(d[mf][nf][2], d[mf][nf][3]);
            *(float2*)(ob + (size_t)o0 * HWSZ + px)       = v0;
            *(float2*)(ob + (size_t)(o0 + 8) * HWSZ + px) = v1;
            s0 += v0.x + v0.y;
            s1 += v1.x + v1.y;
        }
        s0 += __shfl_xor_sync(0xffffffffu, s0, 1);
        s0 += __shfl_xor_sync(0xffffffffu, s0, 2);
        s1 += __shfl_xor_sync(0xffffffffu, s1, 1);
        s1 += __shfl_xor_sync(0xffffffffu, s1, 2);
        if (t == 0) {
            atomicAdd(&g_cp[b * OC + o0], s0);
            atomicAdd(&g_cp[b * OC + o0 + 8], s1);
        }
    }
}

// ---------------- K5: SE channel attention MLP (1 block) ----------------
__global__ void k_chattn(const float* __restrict__ w1, const float* __restrict__ g1, const float* __restrict__ b1,
                         const float* __restrict__ w2, const float* __restrict__ g2, const float* __restrict__ b2) {
    __shared__ float scp[BB*OC];
    __shared__ float sh[BB*16];
    int t = threadIdx.x;
    for (int i = t; i < BB*OC; i += 256) scp[i] = g_cp[i] * (1.0f / HWSZ);
    __syncthreads();
    {
        int b = t >> 4, j = t & 15;
        float a = 0.0f;
        for (int i = 0; i < OC; i++) a += scp[b*OC + i] * w1[j*OC + i];
        a = a * bn_scale(g1[j]) + b1[j];
        sh[t] = fmaxf(a, 0.0f);
    }
    __syncthreads();
    for (int k = 0; k < 8; k++) {
        int idx = t + k*256;
        int b = idx >> 7, i = idx & 127;
        float a = 0.0f;
        for (int j = 0; j < 16; j++) a += sh[b*16 + j] * w2[i*16 + j];
        a = a * bn_scale(g2[i]) + b2[i];
        g_cw[idx] = sigmoidf_(a);
    }
}

// ---------------- K6: spatial mean/max over channels of out*cw ----------------
__global__ void k_spstats() {
    __shared__ float scw[OC];
    int blk = blockIdx.x;
    int b = blk >> 6;
    int t = threadIdx.x;
    if (t < OC) scw[t] = g_cw[b*OC + t];
    __syncthreads();
    int hw = (blk & 63) * 256 + t;
    const float* ob = g_out + (size_t)b * OC * HWSZ + hw;
    float s = 0.0f, m = -1e30f;
    for (int o = 0; o < OC; o++) {
        float v = ob[(size_t)o * HWSZ] * scw[o];
        s += v;
        m = fmaxf(m, v);
    }
    g_mean[b*HWSZ + hw] = s * (1.0f / OC);
    g_max [b*HWSZ + hw] = m;
}

// ---------------- K7: 7x7 spatial-attention conv + sigmoid(bn) ----------------
__global__ void k_spconv(const float* __restrict__ saw, const float* __restrict__ sg, const float* __restrict__ sb) {
    __shared__ float sw_[98];
    int t = threadIdx.x;
    if (t < 98) sw_[t] = saw[t];
    __syncthreads();
    int idx = blockIdx.x * 256 + t;
    int b = idx >> 14;
    int hw = idx & 16383;
    int h = hw >> 7, w = hw & 127;
    float a = 0.0f;
    const float* mb = g_mean + (size_t)b * HWSZ;
    const float* xb = g_max  + (size_t)b * HWSZ;
    for (int kh = 0; kh < 7; kh++) {
        int hh = h + kh - 3;
        if (hh < 0 || hh >= HH) continue;
        for (int kw = 0; kw < 7; kw++) {
            int ww = w + kw - 3;
            if (ww < 0 || ww >= WW) continue;
            int o = hh*WW + ww;
            a += mb[o] * sw_[kh*7 + kw] + xb[o] * sw_[49 + kh*7 + kw];
        }
    }
    a = a * bn_scale(sg[0]) + sb[0];
    g_sw[idx] = sigmoidf_(a);
}

// ---------------- K8: final out = conv*cw*sw + x ----------------
__global__ void k_final(const float* __restrict__ x, float* __restrict__ out) {
    size_t i4 = (size_t)blockIdx.x * 256 + threadIdx.x;
    size_t e = i4 * 4;
    int b  = (int)(e >> 21);
    int o  = (int)((e >> 14) & 127);
    int hw = (int)(e & 16383);
    float cw = g_cw[b*OC + o];
    float4 v  = *(const float4*)(g_out + e);
    float4 xv = ((const float4*)x)[i4];
    float4 sv = *(const float4*)(g_sw + (size_t)b*HWSZ + hw);
    float4 r;
    r.x = v.x * cw * sv.x + xv.x;
    r.y = v.y * cw * sv.y + xv.y;
    r.z = v.z * cw * sv.z + xv.z;
    r.w = v.w * cw * sv.w + xv.w;
    ((float4*)out)[i4] = r;
}

// ---------------- launcher ----------------
extern "C" void kernel_launch(void* const* d_in, const int* in_sizes, int n_in,
                              void* d_out, int out_size) {
    const float* x        = (const float*)d_in[0];
    const float* experts  = (const float*)d_in[1];
    const float* rw1      = (const float*)d_in[2];
    const float* rbn1_g   = (const float*)d_in[3];
    const float* rbn1_b   = (const float*)d_in[4];
    const float* rw2      = (const float*)d_in[5];
    const float* rbn2_g   = (const float*)d_in[6];
    const float* rbn2_b   = (const float*)d_in[7];
    const float* rw3      = (const float*)d_in[8];
    const float* rb3      = (const float*)d_in[9];
    const float* ca_w1    = (const float*)d_in[10];
    const float* ca_bn1_g = (const float*)d_in[11];
    const float* ca_bn1_b = (const float*)d_in[12];
    const float* ca_w2    = (const float*)d_in[13];
    const float* ca_bn2_g = (const float*)d_in[14];
    const float* ca_bn2_b = (const float*)d_in[15];
    const float* sa_w     = (const float*)d_in[16];
    const float* sa_bn_g  = (const float*)d_in[17];
    const float* sa_bn_b  = (const float*)d_in[18];
    float* out = (float*)d_out;

    cudaFuncSetAttribute(k_conv_mma, cudaFuncAttributeMaxDynamicSharedMemorySize, CONV_SMEM);

    k_pool<<<BB*IC, 256>>>(x);
    k_route<<<1, 256>>>(rw1, rbn1_g, rbn1_b, rw2, rbn2_g, rbn2_b, rw3, rb3);
    k_wgen<<<OIK/256, 256>>>(experts);
    k_conv_mma<<<BB*HH, 256, CONV_SMEM>>>(x);
    k_chattn<<<1, 256>>>(ca_w1, ca_bn1_g, ca_bn1_b, ca_w2, ca_bn2_g, ca_bn2_b);
    k_spstats<<<BB*64, 256>>>();
    k_spconv<<<BB*64, 256>>>(sa_w, sa_bn_g, sa_bn_b);
    k_final<<<(BB*OC*HWSZ)/(4*256), 256>>>(x, out);
}